// round 2
// baseline (speedup 1.0000x reference)
#include <cuda_runtime.h>
#include <cstdint>

// ---------------------------------------------------------------------------
// GraphSAGE (3x SAGEConv + BN/ReLU) on B200.
//   - edge_index arrives as int32 (JAX default config downcasts int64).
//   - Build CSR (dst -> list of src) once per launch; reuse for all layers.
//   - Aggregation: one warp per dst node, gather rows + sum, no float atomics.
//   - Layer 2 trick: mean_agg(h2) @ Wl2 == mean_agg(h2 @ Wl2)  (aggregate in 64-d).
//   - GEMM: fp32 tiled SIMT (128x128 / 128x64, 8x8 per thread).
//   - BatchNorm: deterministic 2-stage column reduction + fused BN+ReLU.
// ---------------------------------------------------------------------------

#define NNODES 50000
#define NEDGES 1600000
#define INDIM  128
#define HIDDIM 256
#define OUTDIM 64
#define NB_STATS 512

// ------------------------- scratch (device globals) ------------------------
__device__ float g_agg[(size_t)NNODES * HIDDIM];     // aggregation buffer (max dim 256)
__device__ float g_h1 [(size_t)NNODES * HIDDIM];
__device__ float g_h2 [(size_t)NNODES * HIDDIM];
__device__ float g_y  [(size_t)NNODES * OUTDIM];
__device__ float g_invdeg[NNODES];
__device__ int   g_cnt[NNODES];
__device__ int   g_rowptr[NNODES + 1];
__device__ int   g_fill[NNODES];
__device__ int   g_csr[NEDGES];
__device__ float g_ps[NB_STATS * HIDDIM];
__device__ float g_pq[NB_STATS * HIDDIM];
__device__ float g_scale[HIDDIM];
__device__ float g_shift[HIDDIM];

// ------------------------------- CSR build ---------------------------------
__global__ void zero_int_kernel(int* p, int n) {
    int i = blockIdx.x * blockDim.x + threadIdx.x;
    if (i < n) p[i] = 0;
}

__global__ void hist_kernel(const int* __restrict__ ei, int ne, int* __restrict__ cnt) {
    int e = blockIdx.x * blockDim.x + threadIdx.x;
    if (e < ne) {
        int d = ei[ne + e];                      // dst row of edge_index
        if ((unsigned)d < (unsigned)NNODES)      // defensive: never OOB
            atomicAdd(&cnt[d], 1);
    }
}

// single-block scan over n counters -> rowptr (exclusive at [i], total at [n])
__global__ void scan_kernel(const int* __restrict__ cnt, int* __restrict__ rowptr, int n) {
    __shared__ int sh[1024];
    __shared__ int carry_s;
    int tid = threadIdx.x;
    if (tid == 0) { carry_s = 0; rowptr[0] = 0; }
    __syncthreads();
    for (int base = 0; base < n; base += 1024) {
        int v = (base + tid < n) ? cnt[base + tid] : 0;
        sh[tid] = v;
        __syncthreads();
        for (int off = 1; off < 1024; off <<= 1) {
            int t = (tid >= off) ? sh[tid - off] : 0;
            __syncthreads();
            sh[tid] += t;
            __syncthreads();
        }
        int incl = sh[tid] + carry_s;
        if (base + tid < n) rowptr[base + tid + 1] = incl;
        __syncthreads();
        if (tid == 0) carry_s += sh[1023];
        __syncthreads();
    }
}

__global__ void prep_kernel(const int* __restrict__ cnt, const int* __restrict__ rowptr,
                            int* __restrict__ fill, float* __restrict__ invdeg, int n) {
    int i = blockIdx.x * blockDim.x + threadIdx.x;
    if (i < n) {
        fill[i] = rowptr[i];
        int d = cnt[i];
        invdeg[i] = 1.0f / (float)(d > 0 ? d : 1);
    }
}

__global__ void scatter_kernel(const int* __restrict__ ei, int ne,
                               int* __restrict__ fill, int* __restrict__ csr) {
    int e = blockIdx.x * blockDim.x + threadIdx.x;
    if (e < ne) {
        int s = ei[e];
        int d = ei[ne + e];
        if ((unsigned)d < (unsigned)NNODES && (unsigned)s < (unsigned)NNODES) {
            int pos = atomicAdd(&fill[d], 1);
            if ((unsigned)pos < (unsigned)NEDGES)
                csr[pos] = s;
        }
    }
}

// ------------------------------ aggregation --------------------------------
// One warp per destination node. D in {64, 128, 256}. Each lane owns D/32
// contiguous floats of the row (float4 / float2 vectorized).
template <int D, bool ADD>
__global__ void agg_kernel(const float* __restrict__ X, float* __restrict__ Out,
                           const int* __restrict__ rowptr, const int* __restrict__ csr,
                           const float* __restrict__ invdeg, int n_nodes) {
    int gwarp = (blockIdx.x * blockDim.x + threadIdx.x) >> 5;
    if (gwarp >= n_nodes) return;
    int lane = threadIdx.x & 31;
    constexpr int PL = D / 32;           // floats per lane
    float acc[PL];
#pragma unroll
    for (int i = 0; i < PL; i++) acc[i] = 0.0f;

    int beg = rowptr[gwarp];
    int end = rowptr[gwarp + 1];

    if constexpr (PL >= 4) {
        constexpr int NV = PL / 4;
        int e = beg;
        for (; e + 1 < end; e += 2) {
            int s0 = __ldg(csr + e);
            int s1 = __ldg(csr + e + 1);
            const float4* p0 = reinterpret_cast<const float4*>(X + (size_t)s0 * D + lane * PL);
            const float4* p1 = reinterpret_cast<const float4*>(X + (size_t)s1 * D + lane * PL);
#pragma unroll
            for (int i = 0; i < NV; i++) {
                float4 v0 = __ldg(p0 + i);
                float4 v1 = __ldg(p1 + i);
                acc[4*i+0] += v0.x + v1.x;
                acc[4*i+1] += v0.y + v1.y;
                acc[4*i+2] += v0.z + v1.z;
                acc[4*i+3] += v0.w + v1.w;
            }
        }
        if (e < end) {
            int s0 = __ldg(csr + e);
            const float4* p0 = reinterpret_cast<const float4*>(X + (size_t)s0 * D + lane * PL);
#pragma unroll
            for (int i = 0; i < NV; i++) {
                float4 v0 = __ldg(p0 + i);
                acc[4*i+0] += v0.x;
                acc[4*i+1] += v0.y;
                acc[4*i+2] += v0.z;
                acc[4*i+3] += v0.w;
            }
        }
    } else {
        // PL == 2 (D == 64)
        int e = beg;
        for (; e + 1 < end; e += 2) {
            int s0 = __ldg(csr + e);
            int s1 = __ldg(csr + e + 1);
            float2 v0 = __ldg(reinterpret_cast<const float2*>(X + (size_t)s0 * D + lane * PL));
            float2 v1 = __ldg(reinterpret_cast<const float2*>(X + (size_t)s1 * D + lane * PL));
            acc[0] += v0.x + v1.x;
            acc[1] += v0.y + v1.y;
        }
        if (e < end) {
            int s0 = __ldg(csr + e);
            float2 v0 = __ldg(reinterpret_cast<const float2*>(X + (size_t)s0 * D + lane * PL));
            acc[0] += v0.x;
            acc[1] += v0.y;
        }
    }

    float w = __ldg(invdeg + gwarp);
    float* o = Out + (size_t)gwarp * D + lane * PL;
#pragma unroll
    for (int i = 0; i < PL; i++) {
        if constexpr (ADD) o[i] += acc[i] * w;
        else               o[i]  = acc[i] * w;
    }
}

// --------------------------------- GEMM ------------------------------------
// C[M,N] = A[M,K] @ B[K,N] (+ bias) (+ C if ACC). Row-major everywhere.
// K % BK == 0, N % BN == 0 guaranteed by the call sites. M bounds-checked.
template <int BM, int BN, int BK, int TM, int TN>
__global__ void gemm_kernel(const float* __restrict__ A, const float* __restrict__ B,
                            float* __restrict__ C, int M, int N, int K,
                            const float* __restrict__ bias, int accumulate) {
    constexpr int THREADS = (BM / TM) * (BN / TN);
    __shared__ float As[BK][BM];
    __shared__ float Bs[BK][BN];

    int tid = threadIdx.x;
    int tx = tid % (BN / TN);
    int ty = tid / (BN / TN);
    int block_m = blockIdx.y * BM;
    int block_n = blockIdx.x * BN;

    constexpr int AK4 = BK / 4;
    constexpr int BN4 = BN / 4;
    constexpr int A_LD_ITERS = (BM * BK) / (4 * THREADS);
    constexpr int B_LD_ITERS = (BK * BN) / (4 * THREADS);

    float acc[TM][TN];
#pragma unroll
    for (int i = 0; i < TM; i++)
#pragma unroll
        for (int j = 0; j < TN; j++) acc[i][j] = 0.0f;

    for (int k0 = 0; k0 < K; k0 += BK) {
#pragma unroll
        for (int it = 0; it < A_LD_ITERS; it++) {
            int idx = tid + it * THREADS;
            int ar = idx / AK4;
            int ac = (idx % AK4) * 4;
            int gr = block_m + ar;
            float4 v = make_float4(0.f, 0.f, 0.f, 0.f);
            if (gr < M)
                v = *reinterpret_cast<const float4*>(A + (size_t)gr * K + k0 + ac);
            As[ac + 0][ar] = v.x;
            As[ac + 1][ar] = v.y;
            As[ac + 2][ar] = v.z;
            As[ac + 3][ar] = v.w;
        }
#pragma unroll
        for (int it = 0; it < B_LD_ITERS; it++) {
            int idx = tid + it * THREADS;
            int br = idx / BN4;
            int bc = (idx % BN4) * 4;
            float4 v = *reinterpret_cast<const float4*>(B + (size_t)(k0 + br) * N + block_n + bc);
            *reinterpret_cast<float4*>(&Bs[br][bc]) = v;
        }
        __syncthreads();

#pragma unroll
        for (int kk = 0; kk < BK; kk++) {
            float ar[TM], br[TN];
#pragma unroll
            for (int i = 0; i < TM; i++) ar[i] = As[kk][ty * TM + i];
#pragma unroll
            for (int j = 0; j < TN; j++) br[j] = Bs[kk][tx * TN + j];
#pragma unroll
            for (int i = 0; i < TM; i++)
#pragma unroll
                for (int j = 0; j < TN; j++) acc[i][j] += ar[i] * br[j];
        }
        __syncthreads();
    }

#pragma unroll
    for (int i = 0; i < TM; i++) {
        int gr = block_m + ty * TM + i;
        if (gr >= M) continue;
        size_t rowoff = (size_t)gr * N + block_n + tx * TN;
#pragma unroll
        for (int j = 0; j < TN; j += 4) {
            int col = block_n + tx * TN + j;
            float4 v;
            v.x = acc[i][j + 0];
            v.y = acc[i][j + 1];
            v.z = acc[i][j + 2];
            v.w = acc[i][j + 3];
            if (bias) {
                v.x += __ldg(bias + col + 0);
                v.y += __ldg(bias + col + 1);
                v.z += __ldg(bias + col + 2);
                v.w += __ldg(bias + col + 3);
            }
            if (accumulate) {
                float4 o = *reinterpret_cast<const float4*>(C + rowoff + j);
                v.x += o.x; v.y += o.y; v.z += o.z; v.w += o.w;
            }
            *reinterpret_cast<float4*>(C + rowoff + j) = v;
        }
    }
}

// ------------------------------- BatchNorm ----------------------------------
__global__ void colstats_partial(const float* __restrict__ H, int M,
                                 float* __restrict__ ps, float* __restrict__ pq) {
    int c = threadIdx.x;   // 256 threads = 256 columns
    float s = 0.f, q = 0.f;
    for (int r = blockIdx.x; r < M; r += gridDim.x) {
        float v = H[(size_t)r * HIDDIM + c];
        s += v;
        q += v * v;
    }
    ps[blockIdx.x * HIDDIM + c] = s;
    pq[blockIdx.x * HIDDIM + c] = q;
}

__global__ void colstats_final(const float* __restrict__ ps, const float* __restrict__ pq,
                               int nb, float inv_m,
                               const float* __restrict__ g, const float* __restrict__ be,
                               float* __restrict__ scale, float* __restrict__ shift) {
    int c = threadIdx.x;
    float s = 0.f, q = 0.f;
    for (int b = 0; b < nb; b++) {
        s += ps[b * HIDDIM + c];
        q += pq[b * HIDDIM + c];
    }
    float mu  = s * inv_m;
    float var = q * inv_m - mu * mu;
    float rs  = rsqrtf(var + 1e-5f);
    float sc  = g[c] * rs;
    scale[c] = sc;
    shift[c] = be[c] - mu * sc;
}

__global__ void bnrelu_kernel(float4* __restrict__ H, int n4,
                              const float* __restrict__ sc, const float* __restrict__ sh) {
    int i = blockIdx.x * blockDim.x + threadIdx.x;
    if (i >= n4) return;
    int c = (i * 4) & (HIDDIM - 1);
    float4 v = H[i];
    v.x = fmaxf(v.x * __ldg(sc + c + 0) + __ldg(sh + c + 0), 0.f);
    v.y = fmaxf(v.y * __ldg(sc + c + 1) + __ldg(sh + c + 1), 0.f);
    v.z = fmaxf(v.z * __ldg(sc + c + 2) + __ldg(sh + c + 2), 0.f);
    v.w = fmaxf(v.w * __ldg(sc + c + 3) + __ldg(sh + c + 3), 0.f);
    H[i] = v;
}

// --------------------------------- launch -----------------------------------
extern "C" void kernel_launch(void* const* d_in, const int* in_sizes, int n_in,
                              void* d_out, int out_size) {
    const float* x   = (const float*)d_in[0];
    const int*   ei  = (const int*)d_in[1];       // int32: JAX default downcasts int64
    const float* Wl0 = (const float*)d_in[2];
    const float* bl0 = (const float*)d_in[3];
    const float* Wr0 = (const float*)d_in[4];
    const float* Wl1 = (const float*)d_in[5];
    const float* bl1 = (const float*)d_in[6];
    const float* Wr1 = (const float*)d_in[7];
    const float* Wl2 = (const float*)d_in[8];
    const float* bl2 = (const float*)d_in[9];
    const float* Wr2 = (const float*)d_in[10];
    const float* g0  = (const float*)d_in[11];
    const float* be0 = (const float*)d_in[12];
    const float* g1  = (const float*)d_in[13];
    const float* be1 = (const float*)d_in[14];
    float* out = (float*)d_out;

    const int N  = NNODES;
    const int NE = NEDGES;

    float *agg, *h1, *h2, *y, *invdeg, *ps, *pq, *scale, *shift;
    int *cnt, *rowptr, *fill, *csr;
    cudaGetSymbolAddress((void**)&agg,    g_agg);
    cudaGetSymbolAddress((void**)&h1,     g_h1);
    cudaGetSymbolAddress((void**)&h2,     g_h2);
    cudaGetSymbolAddress((void**)&y,      g_y);
    cudaGetSymbolAddress((void**)&invdeg, g_invdeg);
    cudaGetSymbolAddress((void**)&cnt,    g_cnt);
    cudaGetSymbolAddress((void**)&rowptr, g_rowptr);
    cudaGetSymbolAddress((void**)&fill,   g_fill);
    cudaGetSymbolAddress((void**)&csr,    g_csr);
    cudaGetSymbolAddress((void**)&ps,     g_ps);
    cudaGetSymbolAddress((void**)&pq,     g_pq);
    cudaGetSymbolAddress((void**)&scale,  g_scale);
    cudaGetSymbolAddress((void**)&shift,  g_shift);

    // ---- CSR build ----
    zero_int_kernel<<<(N + 255) / 256, 256>>>(cnt, N);
    hist_kernel<<<(NE + 255) / 256, 256>>>(ei, NE, cnt);
    scan_kernel<<<1, 1024>>>(cnt, rowptr, N);
    prep_kernel<<<(N + 255) / 256, 256>>>(cnt, rowptr, fill, invdeg, N);
    scatter_kernel<<<(NE + 255) / 256, 256>>>(ei, NE, fill, csr);

    const int AGG_BLOCKS = (N + 7) / 8;   // 8 warps per 256-thread block

    // ---- Layer 0: h1 = mean_agg(x) @ Wl0 + bl0 + x @ Wr0 ----
    agg_kernel<INDIM, false><<<AGG_BLOCKS, 256>>>(x, agg, rowptr, csr, invdeg, N);
    {
        dim3 grid(HIDDIM / 128, (N + 127) / 128);
        gemm_kernel<128, 128, 8, 8, 8><<<grid, 256>>>(agg, Wl0, h1, N, HIDDIM, INDIM, bl0, 0);
        gemm_kernel<128, 128, 8, 8, 8><<<grid, 256>>>(x,   Wr0, h1, N, HIDDIM, INDIM, nullptr, 1);
    }
    colstats_partial<<<NB_STATS, HIDDIM>>>(h1, N, ps, pq);
    colstats_final<<<1, HIDDIM>>>(ps, pq, NB_STATS, 1.0f / (float)N, g0, be0, scale, shift);
    bnrelu_kernel<<<(N * HIDDIM / 4 + 255) / 256, 256>>>((float4*)h1, N * HIDDIM / 4, scale, shift);

    // ---- Layer 1: h2 = mean_agg(h1) @ Wl1 + bl1 + h1 @ Wr1 ----
    agg_kernel<HIDDIM, false><<<AGG_BLOCKS, 256>>>(h1, agg, rowptr, csr, invdeg, N);
    {
        dim3 grid(HIDDIM / 128, (N + 127) / 128);
        gemm_kernel<128, 128, 8, 8, 8><<<grid, 256>>>(agg, Wl1, h2, N, HIDDIM, HIDDIM, bl1, 0);
        gemm_kernel<128, 128, 8, 8, 8><<<grid, 256>>>(h1,  Wr1, h2, N, HIDDIM, HIDDIM, nullptr, 1);
    }
    colstats_partial<<<NB_STATS, HIDDIM>>>(h2, N, ps, pq);
    colstats_final<<<1, HIDDIM>>>(ps, pq, NB_STATS, 1.0f / (float)N, g1, be1, scale, shift);
    bnrelu_kernel<<<(N * HIDDIM / 4 + 255) / 256, 256>>>((float4*)h2, N * HIDDIM / 4, scale, shift);

    // ---- Layer 2: out = mean_agg(h2 @ Wl2) + bl2 + h2 @ Wr2 ----
    {
        dim3 grid(OUTDIM / 64, (N + 127) / 128);
        gemm_kernel<128, 64, 8, 8, 8><<<grid, 128>>>(h2, Wl2, y,   N, OUTDIM, HIDDIM, nullptr, 0);
        gemm_kernel<128, 64, 8, 8, 8><<<grid, 128>>>(h2, Wr2, out, N, OUTDIM, HIDDIM, bl2, 0);
    }
    agg_kernel<OUTDIM, true><<<AGG_BLOCKS, 256>>>(y, out, rowptr, csr, invdeg, N);
}

// round 3
// speedup vs baseline: 1.3634x; 1.3634x over previous
#include <cuda_runtime.h>
#include <cstdint>

// ---------------------------------------------------------------------------
// GraphSAGE (3x SAGEConv + BN/ReLU) on B200 / sm_100a.
//   - edge_index is int32.
//   - CSR built once per launch (hist -> fused shuffle-scan/prep -> scatter).
//   - Aggregation: one warp per dst node, float4 gathers, no float atomics.
//   - Layer 2 trick: mean_agg(h2) @ Wl2 == mean_agg(h2 @ Wl2) (aggregate 64-d).
//   - GEMM: TF32 tensor-core mma.sync m16n8k8, dual-A fusion:
//       C = A0@B0 + A1@B1 (+bias) in one kernel (no C read-modify-write).
//   - BatchNorm: deterministic 2-stage column reduction + fused BN+ReLU.
// ---------------------------------------------------------------------------

#define NNODES 50000
#define NEDGES 1600000
#define INDIM  128
#define HIDDIM 256
#define OUTDIM 64
#define NB_STATS 512

// ------------------------- scratch (device globals) ------------------------
__device__ float g_agg[(size_t)NNODES * HIDDIM];
__device__ float g_h1 [(size_t)NNODES * HIDDIM];
__device__ float g_h2 [(size_t)NNODES * HIDDIM];
__device__ float g_y  [(size_t)NNODES * OUTDIM];
__device__ float g_invdeg[NNODES];
__device__ int   g_cnt[NNODES];
__device__ int   g_rowptr[NNODES + 1];
__device__ int   g_fill[NNODES];
__device__ int   g_csr[NEDGES];
__device__ float g_ps[NB_STATS * HIDDIM];
__device__ float g_pq[NB_STATS * HIDDIM];
__device__ float g_scale[HIDDIM];
__device__ float g_shift[HIDDIM];

// ------------------------------- CSR build ---------------------------------
__global__ void zero_int_kernel(int* p, int n) {
    int i = blockIdx.x * blockDim.x + threadIdx.x;
    if (i < n) p[i] = 0;
}

__global__ void hist_kernel(const int* __restrict__ ei, int ne, int* __restrict__ cnt) {
    int e = blockIdx.x * blockDim.x + threadIdx.x;
    if (e < ne) {
        int d = ei[ne + e];
        if ((unsigned)d < (unsigned)NNODES)
            atomicAdd(&cnt[d], 1);
    }
}

// Fused: exclusive-scan rowptr + fill init + invdeg. Single block, shuffle scan.
__global__ void scan_prep_kernel(const int* __restrict__ cnt, int* __restrict__ rowptr,
                                 int* __restrict__ fill, float* __restrict__ invdeg, int n) {
    __shared__ int wsum[32];
    __shared__ int carry_s;
    int tid = threadIdx.x, lane = tid & 31, wid = tid >> 5;
    if (tid == 0) { carry_s = 0; rowptr[0] = 0; }
    __syncthreads();
    for (int base = 0; base < n; base += 1024) {
        int i = base + tid;
        int v = (i < n) ? cnt[i] : 0;
        int s = v;
#pragma unroll
        for (int off = 1; off < 32; off <<= 1) {
            int t = __shfl_up_sync(0xffffffffu, s, off);
            if (lane >= off) s += t;
        }
        if (lane == 31) wsum[wid] = s;
        __syncthreads();
        if (wid == 0) {
            int w = wsum[lane];
#pragma unroll
            for (int off = 1; off < 32; off <<= 1) {
                int t = __shfl_up_sync(0xffffffffu, w, off);
                if (lane >= off) w += t;
            }
            wsum[lane] = w;
        }
        __syncthreads();
        int incl = s + (wid ? wsum[wid - 1] : 0) + carry_s;
        if (i < n) {
            rowptr[i + 1] = incl;
            fill[i] = incl - v;
            invdeg[i] = 1.0f / (float)(v > 0 ? v : 1);
        }
        __syncthreads();
        if (tid == 1023) carry_s = incl;
        __syncthreads();
    }
}

__global__ void scatter_kernel(const int* __restrict__ ei, int ne,
                               int* __restrict__ fill, int* __restrict__ csr) {
    int e = blockIdx.x * blockDim.x + threadIdx.x;
    if (e < ne) {
        int s = ei[e];
        int d = ei[ne + e];
        if ((unsigned)d < (unsigned)NNODES && (unsigned)s < (unsigned)NNODES) {
            int pos = atomicAdd(&fill[d], 1);
            if ((unsigned)pos < (unsigned)NEDGES)
                csr[pos] = s;
        }
    }
}

// ------------------------------ aggregation --------------------------------
template <int D, bool ADD>
__global__ void agg_kernel(const float* __restrict__ X, float* __restrict__ Out,
                           const int* __restrict__ rowptr, const int* __restrict__ csr,
                           const float* __restrict__ invdeg, int n_nodes) {
    int gwarp = (blockIdx.x * blockDim.x + threadIdx.x) >> 5;
    if (gwarp >= n_nodes) return;
    int lane = threadIdx.x & 31;
    constexpr int PL = D / 32;
    float acc[PL];
#pragma unroll
    for (int i = 0; i < PL; i++) acc[i] = 0.0f;

    int beg = rowptr[gwarp];
    int end = rowptr[gwarp + 1];

    if constexpr (PL >= 4) {
        constexpr int NV = PL / 4;
        int e = beg;
        for (; e + 1 < end; e += 2) {
            int s0 = __ldg(csr + e);
            int s1 = __ldg(csr + e + 1);
            const float4* p0 = reinterpret_cast<const float4*>(X + (size_t)s0 * D + lane * PL);
            const float4* p1 = reinterpret_cast<const float4*>(X + (size_t)s1 * D + lane * PL);
#pragma unroll
            for (int i = 0; i < NV; i++) {
                float4 v0 = __ldg(p0 + i);
                float4 v1 = __ldg(p1 + i);
                acc[4*i+0] += v0.x + v1.x;
                acc[4*i+1] += v0.y + v1.y;
                acc[4*i+2] += v0.z + v1.z;
                acc[4*i+3] += v0.w + v1.w;
            }
        }
        if (e < end) {
            int s0 = __ldg(csr + e);
            const float4* p0 = reinterpret_cast<const float4*>(X + (size_t)s0 * D + lane * PL);
#pragma unroll
            for (int i = 0; i < NV; i++) {
                float4 v0 = __ldg(p0 + i);
                acc[4*i+0] += v0.x;
                acc[4*i+1] += v0.y;
                acc[4*i+2] += v0.z;
                acc[4*i+3] += v0.w;
            }
        }
    } else {
        int e = beg;
        for (; e + 1 < end; e += 2) {
            int s0 = __ldg(csr + e);
            int s1 = __ldg(csr + e + 1);
            float2 v0 = __ldg(reinterpret_cast<const float2*>(X + (size_t)s0 * D + lane * PL));
            float2 v1 = __ldg(reinterpret_cast<const float2*>(X + (size_t)s1 * D + lane * PL));
            acc[0] += v0.x + v1.x;
            acc[1] += v0.y + v1.y;
        }
        if (e < end) {
            int s0 = __ldg(csr + e);
            float2 v0 = __ldg(reinterpret_cast<const float2*>(X + (size_t)s0 * D + lane * PL));
            acc[0] += v0.x;
            acc[1] += v0.y;
        }
    }

    float w = __ldg(invdeg + gwarp);
    float* o = Out + (size_t)gwarp * D + lane * PL;
#pragma unroll
    for (int i = 0; i < PL; i++) {
        if constexpr (ADD) o[i] += acc[i] * w;
        else               o[i]  = acc[i] * w;
    }
}

// ------------------------------ TF32 GEMM -----------------------------------
__device__ __forceinline__ unsigned f2tf32(float f) {
    unsigned u;
    asm("cvt.rna.tf32.f32 %0, %1;" : "=r"(u) : "f"(f));
    return u;
}

__device__ __forceinline__ void mma_tf32(float c[4], const unsigned a[4], const unsigned b[2]) {
    asm volatile(
        "mma.sync.aligned.m16n8k8.row.col.f32.tf32.tf32.f32 "
        "{%0,%1,%2,%3}, {%4,%5,%6,%7}, {%8,%9}, {%0,%1,%2,%3};"
        : "+f"(c[0]), "+f"(c[1]), "+f"(c[2]), "+f"(c[3])
        : "r"(a[0]), "r"(a[1]), "r"(a[2]), "r"(a[3]), "r"(b[0]), "r"(b[1]));
}

// C[M,N] = A0[M,K]@B0[K,N] (+ A1[M,K]@B1[K,N]) (+ bias). Row-major.
// 256 threads, 8 warps. Warp tile WM x WN via m16n8k8. BK=32.
template <int BM, int BN, int WM, int WN>
__global__ void gemm_tf32(const float* __restrict__ A0, const float* __restrict__ B0g,
                          const float* __restrict__ A1, const float* __restrict__ B1g,
                          float* __restrict__ C, int M, int N, int K,
                          const float* __restrict__ bias) {
    constexpr int BK = 32, THREADS = 256;
    constexpr int WCOLS = BN / WN;
    constexpr int MT = WM / 16, NT = WN / 8;
    static_assert((BM / WM) * (BN / WN) == 8, "8 warps");

    __shared__ unsigned As[BK][BM + 1];   // [k][m], pad 1 -> conflict-free stores
    __shared__ unsigned Bs[BK][BN + 4];   // [k][n], pad 4 keeps rows 16B-aligned

    int tid = threadIdx.x, lane = tid & 31, warp = tid >> 5;
    int wrow = warp / WCOLS, wcol = warp % WCOLS;
    int block_m = blockIdx.y * BM, block_n = blockIdx.x * BN;
    int g = lane >> 2, q = lane & 3;

    float acc[MT][NT][4];
#pragma unroll
    for (int mt = 0; mt < MT; mt++)
#pragma unroll
        for (int nt = 0; nt < NT; nt++)
#pragma unroll
            for (int r = 0; r < 4; r++) acc[mt][nt][r] = 0.0f;

    const float* Ap = A0;
    const float* Bp = B0g;
    int npass = A1 ? 2 : 1;

    for (int pass = 0; pass < npass; ++pass) {
        for (int k0 = 0; k0 < K; k0 += BK) {
            // Load A tile (BM x 32), transpose into As[k][m], cvt to tf32.
            constexpr int ACH = (BM * BK) / (4 * THREADS);
#pragma unroll
            for (int it = 0; it < ACH; ++it) {
                int chunk = tid + it * THREADS;
                int r = chunk >> 3;             // row within tile (BK/4 = 8 chunks/row)
                int c4 = (chunk & 7) << 2;      // col
                int gr = block_m + r;
                float4 v = make_float4(0.f, 0.f, 0.f, 0.f);
                if (gr < M)
                    v = *reinterpret_cast<const float4*>(Ap + (size_t)gr * K + k0 + c4);
                As[c4 + 0][r] = f2tf32(v.x);
                As[c4 + 1][r] = f2tf32(v.y);
                As[c4 + 2][r] = f2tf32(v.z);
                As[c4 + 3][r] = f2tf32(v.w);
            }
            // Load B tile (32 x BN) row-major, cvt to tf32.
            constexpr int BCH = (BK * BN) / (4 * THREADS);
            constexpr int BROWCH = BN / 4;
#pragma unroll
            for (int it = 0; it < BCH; ++it) {
                int chunk = tid + it * THREADS;
                int r = chunk / BROWCH;
                int c4 = (chunk % BROWCH) * 4;
                float4 v = *reinterpret_cast<const float4*>(Bp + (size_t)(k0 + r) * N + block_n + c4);
                uint4 u;
                u.x = f2tf32(v.x); u.y = f2tf32(v.y); u.z = f2tf32(v.z); u.w = f2tf32(v.w);
                *reinterpret_cast<uint4*>(&Bs[r][c4]) = u;
            }
            __syncthreads();

#pragma unroll
            for (int s = 0; s < BK / 8; ++s) {
                int kq = s * 8 + q;
                unsigned af[MT][4], bf[NT][2];
#pragma unroll
                for (int mt = 0; mt < MT; ++mt) {
                    int m = wrow * WM + mt * 16 + g;
                    af[mt][0] = As[kq][m];
                    af[mt][1] = As[kq][m + 8];
                    af[mt][2] = As[kq + 4][m];
                    af[mt][3] = As[kq + 4][m + 8];
                }
#pragma unroll
                for (int nt = 0; nt < NT; ++nt) {
                    int nn = wcol * WN + nt * 8 + g;
                    bf[nt][0] = Bs[kq][nn];
                    bf[nt][1] = Bs[kq + 4][nn];
                }
#pragma unroll
                for (int mt = 0; mt < MT; ++mt)
#pragma unroll
                    for (int nt = 0; nt < NT; ++nt)
                        mma_tf32(acc[mt][nt], af[mt], bf[nt]);
            }
            __syncthreads();
        }
        Ap = A1;
        Bp = B1g;
    }

    // Epilogue: c0,c1 -> (row, col..col+1); c2,c3 -> (row+8, col..col+1)
#pragma unroll
    for (int mt = 0; mt < MT; ++mt) {
        int r0 = block_m + wrow * WM + mt * 16 + g;
        int r1 = r0 + 8;
#pragma unroll
        for (int nt = 0; nt < NT; ++nt) {
            int cn = block_n + wcol * WN + nt * 8 + q * 2;
            float b0 = 0.f, b1 = 0.f;
            if (bias) { b0 = __ldg(bias + cn); b1 = __ldg(bias + cn + 1); }
            if (r0 < M) {
                float2 t0 = make_float2(acc[mt][nt][0] + b0, acc[mt][nt][1] + b1);
                *reinterpret_cast<float2*>(C + (size_t)r0 * N + cn) = t0;
            }
            if (r1 < M) {
                float2 t1 = make_float2(acc[mt][nt][2] + b0, acc[mt][nt][3] + b1);
                *reinterpret_cast<float2*>(C + (size_t)r1 * N + cn) = t1;
            }
        }
    }
}

// ------------------------------- BatchNorm ----------------------------------
__global__ void colstats_partial(const float* __restrict__ H, int M,
                                 float* __restrict__ ps, float* __restrict__ pq) {
    int c = threadIdx.x;
    float s = 0.f, q = 0.f;
    for (int r = blockIdx.x; r < M; r += gridDim.x) {
        float v = H[(size_t)r * HIDDIM + c];
        s += v;
        q += v * v;
    }
    ps[blockIdx.x * HIDDIM + c] = s;
    pq[blockIdx.x * HIDDIM + c] = q;
}

__global__ void colstats_final(const float* __restrict__ ps, const float* __restrict__ pq,
                               int nb, float inv_m,
                               const float* __restrict__ g, const float* __restrict__ be,
                               float* __restrict__ scale, float* __restrict__ shift) {
    int c = threadIdx.x;
    float s = 0.f, q = 0.f;
    for (int b = 0; b < nb; b++) {
        s += ps[b * HIDDIM + c];
        q += pq[b * HIDDIM + c];
    }
    float mu  = s * inv_m;
    float var = q * inv_m - mu * mu;
    float rs  = rsqrtf(var + 1e-5f);
    float sc  = g[c] * rs;
    scale[c] = sc;
    shift[c] = be[c] - mu * sc;
}

__global__ void bnrelu_kernel(float4* __restrict__ H, int n4,
                              const float* __restrict__ sc, const float* __restrict__ sh) {
    int i = blockIdx.x * blockDim.x + threadIdx.x;
    if (i >= n4) return;
    int c = (i * 4) & (HIDDIM - 1);
    float4 v = H[i];
    v.x = fmaxf(v.x * __ldg(sc + c + 0) + __ldg(sh + c + 0), 0.f);
    v.y = fmaxf(v.y * __ldg(sc + c + 1) + __ldg(sh + c + 1), 0.f);
    v.z = fmaxf(v.z * __ldg(sc + c + 2) + __ldg(sh + c + 2), 0.f);
    v.w = fmaxf(v.w * __ldg(sc + c + 3) + __ldg(sh + c + 3), 0.f);
    H[i] = v;
}

// --------------------------------- launch -----------------------------------
extern "C" void kernel_launch(void* const* d_in, const int* in_sizes, int n_in,
                              void* d_out, int out_size) {
    const float* x   = (const float*)d_in[0];
    const int*   ei  = (const int*)d_in[1];
    const float* Wl0 = (const float*)d_in[2];
    const float* bl0 = (const float*)d_in[3];
    const float* Wr0 = (const float*)d_in[4];
    const float* Wl1 = (const float*)d_in[5];
    const float* bl1 = (const float*)d_in[6];
    const float* Wr1 = (const float*)d_in[7];
    const float* Wl2 = (const float*)d_in[8];
    const float* bl2 = (const float*)d_in[9];
    const float* Wr2 = (const float*)d_in[10];
    const float* g0  = (const float*)d_in[11];
    const float* be0 = (const float*)d_in[12];
    const float* g1  = (const float*)d_in[13];
    const float* be1 = (const float*)d_in[14];
    float* out = (float*)d_out;

    const int N  = NNODES;
    const int NE = NEDGES;

    float *agg, *h1, *h2, *y, *invdeg, *ps, *pq, *scale, *shift;
    int *cnt, *rowptr, *fill, *csr;
    cudaGetSymbolAddress((void**)&agg,    g_agg);
    cudaGetSymbolAddress((void**)&h1,     g_h1);
    cudaGetSymbolAddress((void**)&h2,     g_h2);
    cudaGetSymbolAddress((void**)&y,      g_y);
    cudaGetSymbolAddress((void**)&invdeg, g_invdeg);
    cudaGetSymbolAddress((void**)&cnt,    g_cnt);
    cudaGetSymbolAddress((void**)&rowptr, g_rowptr);
    cudaGetSymbolAddress((void**)&fill,   g_fill);
    cudaGetSymbolAddress((void**)&csr,    g_csr);
    cudaGetSymbolAddress((void**)&ps,     g_ps);
    cudaGetSymbolAddress((void**)&pq,     g_pq);
    cudaGetSymbolAddress((void**)&scale,  g_scale);
    cudaGetSymbolAddress((void**)&shift,  g_shift);

    // ---- CSR build ----
    zero_int_kernel<<<(N + 255) / 256, 256>>>(cnt, N);
    hist_kernel<<<(NE + 255) / 256, 256>>>(ei, NE, cnt);
    scan_prep_kernel<<<1, 1024>>>(cnt, rowptr, fill, invdeg, N);
    scatter_kernel<<<(NE + 255) / 256, 256>>>(ei, NE, fill, csr);

    const int AGG_BLOCKS = (N + 7) / 8;

    // ---- Layer 0: h1 = mean_agg(x) @ Wl0 + x @ Wr0 + bl0 ----
    agg_kernel<INDIM, false><<<AGG_BLOCKS, 256>>>(x, agg, rowptr, csr, invdeg, N);
    {
        dim3 grid(HIDDIM / 128, (N + 127) / 128);
        gemm_tf32<128, 128, 64, 32><<<grid, 256>>>(agg, Wl0, x, Wr0, h1, N, HIDDIM, INDIM, bl0);
    }
    colstats_partial<<<NB_STATS, HIDDIM>>>(h1, N, ps, pq);
    colstats_final<<<1, HIDDIM>>>(ps, pq, NB_STATS, 1.0f / (float)N, g0, be0, scale, shift);
    bnrelu_kernel<<<(N * HIDDIM / 4 + 255) / 256, 256>>>((float4*)h1, N * HIDDIM / 4, scale, shift);

    // ---- Layer 1: h2 = mean_agg(h1) @ Wl1 + h1 @ Wr1 + bl1 ----
    agg_kernel<HIDDIM, false><<<AGG_BLOCKS, 256>>>(h1, agg, rowptr, csr, invdeg, N);
    {
        dim3 grid(HIDDIM / 128, (N + 127) / 128);
        gemm_tf32<128, 128, 64, 32><<<grid, 256>>>(agg, Wl1, h1, Wr1, h2, N, HIDDIM, HIDDIM, bl1);
    }
    colstats_partial<<<NB_STATS, HIDDIM>>>(h2, N, ps, pq);
    colstats_final<<<1, HIDDIM>>>(ps, pq, NB_STATS, 1.0f / (float)N, g1, be1, scale, shift);
    bnrelu_kernel<<<(N * HIDDIM / 4 + 255) / 256, 256>>>((float4*)h2, N * HIDDIM / 4, scale, shift);

    // ---- Layer 2: out = mean_agg(h2 @ Wl2) + h2 @ Wr2 + bl2 ----
    {
        dim3 grid(OUTDIM / 64, (N + 127) / 128);
        gemm_tf32<128, 64, 32, 32><<<grid, 256>>>(h2, Wl2, nullptr, nullptr, y,   N, OUTDIM, HIDDIM, nullptr);
        gemm_tf32<128, 64, 32, 32><<<grid, 256>>>(h2, Wr2, nullptr, nullptr, out, N, OUTDIM, HIDDIM, bl2);
    }
    agg_kernel<OUTDIM, true><<<AGG_BLOCKS, 256>>>(y, out, rowptr, csr, invdeg, N);
}

// round 5
// speedup vs baseline: 1.4437x; 1.0589x over previous
#include <cuda_runtime.h>
#include <cstdint>

// ---------------------------------------------------------------------------
// GraphSAGE (3x SAGEConv + BN/ReLU) on B200 / sm_100a.
//   - CSR built once per launch; reused by all layers.
//   - Aggregation: one warp per dst node, float4 gathers; BN+ReLU fused into
//     the gather (h1/h2 stay raw — no separate bnrelu pass).
//   - GEMM: TF32 mma.sync m16n8k8, dual-A fusion (C = A0@B0 + A1@B1 + bias),
//     double-buffered DYNAMIC smem + register-staged prefetch, 1 sync/K-tile,
//     optional per-k-column affine+ReLU on A during load.
//   - Layer 2 trick: mean_agg(act(h2)) @ Wl2 == mean_agg(act(h2) @ Wl2).
// ---------------------------------------------------------------------------

#define NNODES 50000
#define NEDGES 1600000
#define INDIM  128
#define HIDDIM 256
#define OUTDIM 64
#define NB_STATS 512

// ------------------------- scratch (device globals) ------------------------
__device__ float g_agg[(size_t)NNODES * HIDDIM];
__device__ float g_h1 [(size_t)NNODES * HIDDIM];
__device__ float g_h2 [(size_t)NNODES * HIDDIM];
__device__ float g_y  [(size_t)NNODES * OUTDIM];
__device__ float g_invdeg[NNODES];
__device__ int   g_cnt[NNODES];
__device__ int   g_rowptr[NNODES + 1];
__device__ int   g_fill[NNODES];
__device__ int   g_csr[NEDGES];
__device__ float g_ps[NB_STATS * HIDDIM];
__device__ float g_pq[NB_STATS * HIDDIM];
__device__ __align__(16) float g_scale[HIDDIM];
__device__ __align__(16) float g_shift[HIDDIM];

// ------------------------------- CSR build ---------------------------------
__global__ void zero_int_kernel(int* p, int n) {
    int i = blockIdx.x * blockDim.x + threadIdx.x;
    if (i < n) p[i] = 0;
}

__global__ void hist_kernel(const int* __restrict__ ei, int ne, int* __restrict__ cnt) {
    int e = blockIdx.x * blockDim.x + threadIdx.x;
    if (e < ne) {
        int d = ei[ne + e];
        if ((unsigned)d < (unsigned)NNODES)
            atomicAdd(&cnt[d], 1);
    }
}

__global__ void scan_prep_kernel(const int* __restrict__ cnt, int* __restrict__ rowptr,
                                 int* __restrict__ fill, float* __restrict__ invdeg, int n) {
    __shared__ int wsum[32];
    __shared__ int carry_s;
    int tid = threadIdx.x, lane = tid & 31, wid = tid >> 5;
    if (tid == 0) { carry_s = 0; rowptr[0] = 0; }
    __syncthreads();
    for (int base = 0; base < n; base += 1024) {
        int i = base + tid;
        int v = (i < n) ? cnt[i] : 0;
        int s = v;
#pragma unroll
        for (int off = 1; off < 32; off <<= 1) {
            int t = __shfl_up_sync(0xffffffffu, s, off);
            if (lane >= off) s += t;
        }
        if (lane == 31) wsum[wid] = s;
        __syncthreads();
        if (wid == 0) {
            int w = wsum[lane];
#pragma unroll
            for (int off = 1; off < 32; off <<= 1) {
                int t = __shfl_up_sync(0xffffffffu, w, off);
                if (lane >= off) w += t;
            }
            wsum[lane] = w;
        }
        __syncthreads();
        int incl = s + (wid ? wsum[wid - 1] : 0) + carry_s;
        if (i < n) {
            rowptr[i + 1] = incl;
            fill[i] = incl - v;
            invdeg[i] = 1.0f / (float)(v > 0 ? v : 1);
        }
        __syncthreads();
        if (tid == 1023) carry_s = incl;
        __syncthreads();
    }
}

__global__ void scatter_kernel(const int* __restrict__ ei, int ne,
                               int* __restrict__ fill, int* __restrict__ csr) {
    int e = blockIdx.x * blockDim.x + threadIdx.x;
    if (e < ne) {
        int s = ei[e];
        int d = ei[ne + e];
        if ((unsigned)d < (unsigned)NNODES && (unsigned)s < (unsigned)NNODES) {
            int pos = atomicAdd(&fill[d], 1);
            if ((unsigned)pos < (unsigned)NEDGES)
                csr[pos] = s;
        }
    }
}

// ------------------------------ aggregation --------------------------------
template <int D, bool ADD, bool ACT>
__global__ void agg_kernel(const float* __restrict__ X, float* __restrict__ Out,
                           const int* __restrict__ rowptr, const int* __restrict__ csr,
                           const float* __restrict__ invdeg, int n_nodes,
                           const float* __restrict__ sc, const float* __restrict__ sh) {
    int gwarp = (blockIdx.x * blockDim.x + threadIdx.x) >> 5;
    if (gwarp >= n_nodes) return;
    int lane = threadIdx.x & 31;
    constexpr int PL = D / 32;
    float acc[PL];
    float lsc[PL], lsh[PL];
#pragma unroll
    for (int i = 0; i < PL; i++) {
        acc[i] = 0.0f;
        if constexpr (ACT) {
            lsc[i] = __ldg(sc + lane * PL + i);
            lsh[i] = __ldg(sh + lane * PL + i);
        }
    }

    int beg = rowptr[gwarp];
    int end = rowptr[gwarp + 1];

    if constexpr (PL >= 4) {
        constexpr int NV = PL / 4;
        int e = beg;
        for (; e + 1 < end; e += 2) {
            int s0 = __ldg(csr + e);
            int s1 = __ldg(csr + e + 1);
            const float4* p0 = reinterpret_cast<const float4*>(X + (size_t)s0 * D + lane * PL);
            const float4* p1 = reinterpret_cast<const float4*>(X + (size_t)s1 * D + lane * PL);
#pragma unroll
            for (int i = 0; i < NV; i++) {
                float4 v0 = __ldg(p0 + i);
                float4 v1 = __ldg(p1 + i);
                if constexpr (ACT) {
                    v0.x = fmaxf(v0.x * lsc[4*i+0] + lsh[4*i+0], 0.f);
                    v0.y = fmaxf(v0.y * lsc[4*i+1] + lsh[4*i+1], 0.f);
                    v0.z = fmaxf(v0.z * lsc[4*i+2] + lsh[4*i+2], 0.f);
                    v0.w = fmaxf(v0.w * lsc[4*i+3] + lsh[4*i+3], 0.f);
                    v1.x = fmaxf(v1.x * lsc[4*i+0] + lsh[4*i+0], 0.f);
                    v1.y = fmaxf(v1.y * lsc[4*i+1] + lsh[4*i+1], 0.f);
                    v1.z = fmaxf(v1.z * lsc[4*i+2] + lsh[4*i+2], 0.f);
                    v1.w = fmaxf(v1.w * lsc[4*i+3] + lsh[4*i+3], 0.f);
                }
                acc[4*i+0] += v0.x + v1.x;
                acc[4*i+1] += v0.y + v1.y;
                acc[4*i+2] += v0.z + v1.z;
                acc[4*i+3] += v0.w + v1.w;
            }
        }
        if (e < end) {
            int s0 = __ldg(csr + e);
            const float4* p0 = reinterpret_cast<const float4*>(X + (size_t)s0 * D + lane * PL);
#pragma unroll
            for (int i = 0; i < NV; i++) {
                float4 v0 = __ldg(p0 + i);
                if constexpr (ACT) {
                    v0.x = fmaxf(v0.x * lsc[4*i+0] + lsh[4*i+0], 0.f);
                    v0.y = fmaxf(v0.y * lsc[4*i+1] + lsh[4*i+1], 0.f);
                    v0.z = fmaxf(v0.z * lsc[4*i+2] + lsh[4*i+2], 0.f);
                    v0.w = fmaxf(v0.w * lsc[4*i+3] + lsh[4*i+3], 0.f);
                }
                acc[4*i+0] += v0.x;
                acc[4*i+1] += v0.y;
                acc[4*i+2] += v0.z;
                acc[4*i+3] += v0.w;
            }
        }
    } else {
        int e = beg;
        for (; e + 1 < end; e += 2) {
            int s0 = __ldg(csr + e);
            int s1 = __ldg(csr + e + 1);
            float2 v0 = __ldg(reinterpret_cast<const float2*>(X + (size_t)s0 * D + lane * PL));
            float2 v1 = __ldg(reinterpret_cast<const float2*>(X + (size_t)s1 * D + lane * PL));
            acc[0] += v0.x + v1.x;
            acc[1] += v0.y + v1.y;
        }
        if (e < end) {
            int s0 = __ldg(csr + e);
            float2 v0 = __ldg(reinterpret_cast<const float2*>(X + (size_t)s0 * D + lane * PL));
            acc[0] += v0.x;
            acc[1] += v0.y;
        }
    }

    float w = __ldg(invdeg + gwarp);
    float* o = Out + (size_t)gwarp * D + lane * PL;
#pragma unroll
    for (int i = 0; i < PL; i++) {
        if constexpr (ADD) o[i] += acc[i] * w;
        else               o[i]  = acc[i] * w;
    }
}

// ------------------------------ TF32 GEMM -----------------------------------
__device__ __forceinline__ unsigned f2tf32(float f) {
    unsigned u;
    asm("cvt.rna.tf32.f32 %0, %1;" : "=r"(u) : "f"(f));
    return u;
}

__device__ __forceinline__ void mma_tf32(float c[4], const unsigned a[4], const unsigned b[2]) {
    asm volatile(
        "mma.sync.aligned.m16n8k8.row.col.f32.tf32.tf32.f32 "
        "{%0,%1,%2,%3}, {%4,%5,%6,%7}, {%8,%9}, {%0,%1,%2,%3};"
        : "+f"(c[0]), "+f"(c[1]), "+f"(c[2]), "+f"(c[3])
        : "r"(a[0]), "r"(a[1]), "r"(a[2]), "r"(a[3]), "r"(b[0]), "r"(b[1]));
}

// C = act0(A0)@B0 (+ act1(A1)@B1) (+ bias). actX applied per k-column if scX!=null.
// Dynamic smem: [2][BK][BM+1] for As, then [2][BK][BN+4] for Bs (unsigned).
template <int BM, int BN, int WM, int WN>
__global__ void gemm_tf32(const float* __restrict__ A0, const float* __restrict__ B0g,
                          const float* __restrict__ sc0, const float* __restrict__ sh0,
                          const float* __restrict__ A1, const float* __restrict__ B1g,
                          const float* __restrict__ sc1, const float* __restrict__ sh1,
                          float* __restrict__ C, int M, int N, int K,
                          const float* __restrict__ bias) {
    constexpr int BK = 32, THREADS = 256;
    constexpr int WCOLS = BN / WN;
    constexpr int MT = WM / 16, NT = WN / 8;
    constexpr int ACH = (BM * BK) / (4 * THREADS);
    constexpr int BCH = (BK * BN) / (4 * THREADS);
    constexpr int BROWCH = BN / 4;
    constexpr int ASTRIDE = BM + 1;      // per-k row stride of As
    constexpr int BSTRIDE = BN + 4;      // per-k row stride of Bs
    static_assert((BM / WM) * (BN / WN) == 8, "8 warps");

    extern __shared__ unsigned smem_u[];
    unsigned* Asm = smem_u;                         // [2][BK][ASTRIDE]
    unsigned* Bsm = smem_u + 2 * BK * ASTRIDE;      // [2][BK][BSTRIDE]
#define AS(b, k, m) Asm[((b) * BK + (k)) * ASTRIDE + (m)]
#define BS(b, k, n) Bsm[((b) * BK + (k)) * BSTRIDE + (n)]

    int tid = threadIdx.x, lane = tid & 31, warp = tid >> 5;
    int wrow = warp / WCOLS, wcol = warp % WCOLS;
    int block_m = blockIdx.y * BM, block_n = blockIdx.x * BN;
    int g = lane >> 2, q = lane & 3;

    float acc[MT][NT][4];
#pragma unroll
    for (int mt = 0; mt < MT; mt++)
#pragma unroll
        for (int nt = 0; nt < NT; nt++)
#pragma unroll
            for (int r = 0; r < 4; r++) acc[mt][nt][r] = 0.0f;

    const int kiters = K / BK;
    const int npass = A1 ? 2 : 1;
    const int total = npass * kiters;

    float4 ra[ACH], rb[BCH];

    auto load_stage = [&](int it) {
        int pass = it / kiters;
        int k0 = (it - pass * kiters) * BK;
        const float* Ap = pass ? A1 : A0;
        const float* Bp = pass ? B1g : B0g;
#pragma unroll
        for (int i = 0; i < ACH; i++) {
            int chunk = tid + i * THREADS;
            int r = chunk >> 3;
            int c4 = (chunk & 7) << 2;
            int gr = block_m + r;
            float4 v = make_float4(0.f, 0.f, 0.f, 0.f);
            if (gr < M)
                v = *reinterpret_cast<const float4*>(Ap + (size_t)gr * K + k0 + c4);
            ra[i] = v;
        }
#pragma unroll
        for (int i = 0; i < BCH; i++) {
            int chunk = tid + i * THREADS;
            int r = chunk / BROWCH;
            int c4 = (chunk % BROWCH) * 4;
            rb[i] = *reinterpret_cast<const float4*>(Bp + (size_t)(k0 + r) * N + block_n + c4);
        }
    };

    auto store_stage = [&](int it, int buf) {
        int pass = it / kiters;
        int k0 = (it - pass * kiters) * BK;
        const float* sc = pass ? sc1 : sc0;
        const float* sh = pass ? sh1 : sh0;
#pragma unroll
        for (int i = 0; i < ACH; i++) {
            int chunk = tid + i * THREADS;
            int r = chunk >> 3;
            int c4 = (chunk & 7) << 2;
            float4 v = ra[i];
            if (sc) {
                float4 s = *reinterpret_cast<const float4*>(sc + k0 + c4);
                float4 t = *reinterpret_cast<const float4*>(sh + k0 + c4);
                v.x = fmaxf(v.x * s.x + t.x, 0.f);
                v.y = fmaxf(v.y * s.y + t.y, 0.f);
                v.z = fmaxf(v.z * s.z + t.z, 0.f);
                v.w = fmaxf(v.w * s.w + t.w, 0.f);
            }
            AS(buf, c4 + 0, r) = f2tf32(v.x);
            AS(buf, c4 + 1, r) = f2tf32(v.y);
            AS(buf, c4 + 2, r) = f2tf32(v.z);
            AS(buf, c4 + 3, r) = f2tf32(v.w);
        }
#pragma unroll
        for (int i = 0; i < BCH; i++) {
            int chunk = tid + i * THREADS;
            int r = chunk / BROWCH;
            int c4 = (chunk % BROWCH) * 4;
            uint4 u;
            u.x = f2tf32(rb[i].x); u.y = f2tf32(rb[i].y);
            u.z = f2tf32(rb[i].z); u.w = f2tf32(rb[i].w);
            *reinterpret_cast<uint4*>(&BS(buf, r, c4)) = u;
        }
    };

    load_stage(0);
    int buf = 0;
    for (int it = 0; it < total; ++it) {
        store_stage(it, buf);
        __syncthreads();
        if (it + 1 < total) load_stage(it + 1);

#pragma unroll
        for (int s = 0; s < BK / 8; ++s) {
            int kq = s * 8 + q;
            unsigned af[MT][4], bf[NT][2];
#pragma unroll
            for (int mt = 0; mt < MT; ++mt) {
                int m = wrow * WM + mt * 16 + g;
                af[mt][0] = AS(buf, kq, m);
                af[mt][1] = AS(buf, kq, m + 8);
                af[mt][2] = AS(buf, kq + 4, m);
                af[mt][3] = AS(buf, kq + 4, m + 8);
            }
#pragma unroll
            for (int nt = 0; nt < NT; ++nt) {
                int nn = wcol * WN + nt * 8 + g;
                bf[nt][0] = BS(buf, kq, nn);
                bf[nt][1] = BS(buf, kq + 4, nn);
            }
#pragma unroll
            for (int mt = 0; mt < MT; ++mt)
#pragma unroll
                for (int nt = 0; nt < NT; ++nt)
                    mma_tf32(acc[mt][nt], af[mt], bf[nt]);
        }
        buf ^= 1;
    }

#pragma unroll
    for (int mt = 0; mt < MT; ++mt) {
        int r0 = block_m + wrow * WM + mt * 16 + g;
        int r1 = r0 + 8;
#pragma unroll
        for (int nt = 0; nt < NT; ++nt) {
            int cn = block_n + wcol * WN + nt * 8 + q * 2;
            float b0 = 0.f, b1 = 0.f;
            if (bias) { b0 = __ldg(bias + cn); b1 = __ldg(bias + cn + 1); }
            if (r0 < M) {
                float2 t0 = make_float2(acc[mt][nt][0] + b0, acc[mt][nt][1] + b1);
                *reinterpret_cast<float2*>(C + (size_t)r0 * N + cn) = t0;
            }
            if (r1 < M) {
                float2 t1 = make_float2(acc[mt][nt][2] + b0, acc[mt][nt][3] + b1);
                *reinterpret_cast<float2*>(C + (size_t)r1 * N + cn) = t1;
            }
        }
    }
#undef AS
#undef BS
}

// ------------------------------- BatchNorm ----------------------------------
__global__ void colstats_partial(const float* __restrict__ H, int M,
                                 float* __restrict__ ps, float* __restrict__ pq) {
    int c = threadIdx.x;
    float s = 0.f, q = 0.f;
    for (int r = blockIdx.x; r < M; r += gridDim.x) {
        float v = H[(size_t)r * HIDDIM + c];
        s += v;
        q += v * v;
    }
    ps[blockIdx.x * HIDDIM + c] = s;
    pq[blockIdx.x * HIDDIM + c] = q;
}

__global__ void colstats_final(const float* __restrict__ ps, const float* __restrict__ pq,
                               int nb, float inv_m,
                               const float* __restrict__ g, const float* __restrict__ be,
                               float* __restrict__ scale, float* __restrict__ shift) {
    int c = threadIdx.x;
    float s = 0.f, q = 0.f;
    for (int b = 0; b < nb; b++) {
        s += ps[b * HIDDIM + c];
        q += pq[b * HIDDIM + c];
    }
    float mu  = s * inv_m;
    float var = q * inv_m - mu * mu;
    float rs  = rsqrtf(var + 1e-5f);
    float sc  = g[c] * rs;
    scale[c] = sc;
    shift[c] = be[c] - mu * sc;
}

// --------------------------------- launch -----------------------------------
extern "C" void kernel_launch(void* const* d_in, const int* in_sizes, int n_in,
                              void* d_out, int out_size) {
    const float* x   = (const float*)d_in[0];
    const int*   ei  = (const int*)d_in[1];
    const float* Wl0 = (const float*)d_in[2];
    const float* bl0 = (const float*)d_in[3];
    const float* Wr0 = (const float*)d_in[4];
    const float* Wl1 = (const float*)d_in[5];
    const float* bl1 = (const float*)d_in[6];
    const float* Wr1 = (const float*)d_in[7];
    const float* Wl2 = (const float*)d_in[8];
    const float* bl2 = (const float*)d_in[9];
    const float* Wr2 = (const float*)d_in[10];
    const float* g0  = (const float*)d_in[11];
    const float* be0 = (const float*)d_in[12];
    const float* g1  = (const float*)d_in[13];
    const float* be1 = (const float*)d_in[14];
    float* out = (float*)d_out;

    const int N  = NNODES;
    const int NE = NEDGES;

    float *agg, *h1, *h2, *y, *invdeg, *ps, *pq, *scale, *shift;
    int *cnt, *rowptr, *fill, *csr;
    cudaGetSymbolAddress((void**)&agg,    g_agg);
    cudaGetSymbolAddress((void**)&h1,     g_h1);
    cudaGetSymbolAddress((void**)&h2,     g_h2);
    cudaGetSymbolAddress((void**)&y,      g_y);
    cudaGetSymbolAddress((void**)&invdeg, g_invdeg);
    cudaGetSymbolAddress((void**)&cnt,    g_cnt);
    cudaGetSymbolAddress((void**)&rowptr, g_rowptr);
    cudaGetSymbolAddress((void**)&fill,   g_fill);
    cudaGetSymbolAddress((void**)&csr,    g_csr);
    cudaGetSymbolAddress((void**)&ps,     g_ps);
    cudaGetSymbolAddress((void**)&pq,     g_pq);
    cudaGetSymbolAddress((void**)&scale,  g_scale);
    cudaGetSymbolAddress((void**)&shift,  g_shift);

    // Dynamic smem sizes (unsigned elements * 4 bytes)
    const int SMEM_BIG   = (2 * 32 * (128 + 1) + 2 * 32 * (128 + 4)) * 4;  // 66816 B
    const int SMEM_SMALL = (2 * 32 * (128 + 1) + 2 * 32 * (64 + 4))  * 4;  // 50432 B
    static int smem_set = 0;
    if (!smem_set) {
        cudaFuncSetAttribute(gemm_tf32<128, 128, 64, 32>,
                             cudaFuncAttributeMaxDynamicSharedMemorySize, SMEM_BIG);
        cudaFuncSetAttribute(gemm_tf32<128, 64, 32, 32>,
                             cudaFuncAttributeMaxDynamicSharedMemorySize, SMEM_SMALL);
        smem_set = 1;
    }

    // ---- CSR build ----
    zero_int_kernel<<<(N + 255) / 256, 256>>>(cnt, N);
    hist_kernel<<<(NE + 255) / 256, 256>>>(ei, NE, cnt);
    scan_prep_kernel<<<1, 1024>>>(cnt, rowptr, fill, invdeg, N);
    scatter_kernel<<<(NE + 255) / 256, 256>>>(ei, NE, fill, csr);

    const int AGG_BLOCKS = (N + 7) / 8;

    // ---- Layer 0: h1 = mean_agg(x) @ Wl0 + x @ Wr0 + bl0  (raw, pre-BN) ----
    agg_kernel<INDIM, false, false><<<AGG_BLOCKS, 256>>>(x, agg, rowptr, csr, invdeg, N, nullptr, nullptr);
    {
        dim3 grid(HIDDIM / 128, (N + 127) / 128);
        gemm_tf32<128, 128, 64, 32><<<grid, 256, SMEM_BIG>>>(agg, Wl0, nullptr, nullptr,
                                                             x,   Wr0, nullptr, nullptr,
                                                             h1, N, HIDDIM, INDIM, bl0);
    }
    colstats_partial<<<NB_STATS, HIDDIM>>>(h1, N, ps, pq);
    colstats_final<<<1, HIDDIM>>>(ps, pq, NB_STATS, 1.0f / (float)N, g0, be0, scale, shift);

    // ---- Layer 1: h2 = mean_agg(act0(h1)) @ Wl1 + act0(h1) @ Wr1 + bl1 ----
    agg_kernel<HIDDIM, false, true><<<AGG_BLOCKS, 256>>>(h1, agg, rowptr, csr, invdeg, N, scale, shift);
    {
        dim3 grid(HIDDIM / 128, (N + 127) / 128);
        gemm_tf32<128, 128, 64, 32><<<grid, 256, SMEM_BIG>>>(agg, Wl1, nullptr, nullptr,
                                                             h1,  Wr1, scale, shift,
                                                             h2, N, HIDDIM, HIDDIM, bl1);
    }
    colstats_partial<<<NB_STATS, HIDDIM>>>(h2, N, ps, pq);
    colstats_final<<<1, HIDDIM>>>(ps, pq, NB_STATS, 1.0f / (float)N, g1, be1, scale, shift);

    // ---- Layer 2: out = mean_agg(act1(h2) @ Wl2) + act1(h2) @ Wr2 + bl2 ----
    {
        dim3 grid(OUTDIM / 64, (N + 127) / 128);
        gemm_tf32<128, 64, 32, 32><<<grid, 256, SMEM_SMALL>>>(h2, Wl2, scale, shift,
                                                              nullptr, nullptr, nullptr, nullptr,
                                                              y, N, OUTDIM, HIDDIM, nullptr);
        gemm_tf32<128, 64, 32, 32><<<grid, 256, SMEM_SMALL>>>(h2, Wr2, scale, shift,
                                                              nullptr, nullptr, nullptr, nullptr,
                                                              out, N, OUTDIM, HIDDIM, bl2);
    }
    agg_kernel<OUTDIM, true, false><<<AGG_BLOCKS, 256>>>(y, out, rowptr, csr, invdeg, N, nullptr, nullptr);
}

// round 6
// speedup vs baseline: 1.4991x; 1.0383x over previous
#include <cuda_runtime.h>
#include <cstdint>

// ---------------------------------------------------------------------------
// GraphSAGE (3x SAGEConv + BN/ReLU) on B200 / sm_100a.
//   - CSR built once per launch; reused by all layers.
//   - Aggregation: 1-2 warps per dst node (128 floats per warp), 4-edge unroll
//     with dual accumulator banks (MLP 4-8); BN+ReLU fused into the gather.
//   - GEMM: TF32 mma.sync m16n8k8, dual-A fusion, double-buffered dynamic smem.
//   - Layer 2 trick: mean_agg(act(h2)) @ Wl2 == mean_agg(act(h2) @ Wl2).
// ---------------------------------------------------------------------------

#define NNODES 50000
#define NEDGES 1600000
#define INDIM  128
#define HIDDIM 256
#define OUTDIM 64
#define NB_STATS 512

// ------------------------- scratch (device globals) ------------------------
__device__ float g_agg[(size_t)NNODES * HIDDIM];
__device__ float g_h1 [(size_t)NNODES * HIDDIM];
__device__ float g_h2 [(size_t)NNODES * HIDDIM];
__device__ float g_y  [(size_t)NNODES * OUTDIM];
__device__ float g_invdeg[NNODES];
__device__ int   g_cnt[NNODES];
__device__ int   g_rowptr[NNODES + 1];
__device__ int   g_fill[NNODES];
__device__ int   g_csr[NEDGES];
__device__ float g_ps[NB_STATS * HIDDIM];
__device__ float g_pq[NB_STATS * HIDDIM];
__device__ __align__(16) float g_scale[HIDDIM];
__device__ __align__(16) float g_shift[HIDDIM];

// ------------------------------- CSR build ---------------------------------
__global__ void zero_int_kernel(int* p, int n) {
    int i = blockIdx.x * blockDim.x + threadIdx.x;
    if (i < n) p[i] = 0;
}

__global__ void hist_kernel(const int* __restrict__ ei, int ne, int* __restrict__ cnt) {
    int e = blockIdx.x * blockDim.x + threadIdx.x;
    if (e < ne) {
        int d = ei[ne + e];
        if ((unsigned)d < (unsigned)NNODES)
            atomicAdd(&cnt[d], 1);
    }
}

__global__ void scan_prep_kernel(const int* __restrict__ cnt, int* __restrict__ rowptr,
                                 int* __restrict__ fill, float* __restrict__ invdeg, int n) {
    __shared__ int wsum[32];
    __shared__ int carry_s;
    int tid = threadIdx.x, lane = tid & 31, wid = tid >> 5;
    if (tid == 0) { carry_s = 0; rowptr[0] = 0; }
    __syncthreads();
    for (int base = 0; base < n; base += 1024) {
        int i = base + tid;
        int v = (i < n) ? cnt[i] : 0;
        int s = v;
#pragma unroll
        for (int off = 1; off < 32; off <<= 1) {
            int t = __shfl_up_sync(0xffffffffu, s, off);
            if (lane >= off) s += t;
        }
        if (lane == 31) wsum[wid] = s;
        __syncthreads();
        if (wid == 0) {
            int w = wsum[lane];
#pragma unroll
            for (int off = 1; off < 32; off <<= 1) {
                int t = __shfl_up_sync(0xffffffffu, w, off);
                if (lane >= off) w += t;
            }
            wsum[lane] = w;
        }
        __syncthreads();
        int incl = s + (wid ? wsum[wid - 1] : 0) + carry_s;
        if (i < n) {
            rowptr[i + 1] = incl;
            fill[i] = incl - v;
            invdeg[i] = 1.0f / (float)(v > 0 ? v : 1);
        }
        __syncthreads();
        if (tid == 1023) carry_s = incl;
        __syncthreads();
    }
}

__global__ void scatter_kernel(const int* __restrict__ ei, int ne,
                               int* __restrict__ fill, int* __restrict__ csr) {
    int e = blockIdx.x * blockDim.x + threadIdx.x;
    if (e < ne) {
        int s = ei[e];
        int d = ei[ne + e];
        if ((unsigned)d < (unsigned)NNODES && (unsigned)s < (unsigned)NNODES) {
            int pos = atomicAdd(&fill[d], 1);
            if ((unsigned)pos < (unsigned)NEDGES)
                csr[pos] = s;
        }
    }
}

// ------------------------------ aggregation --------------------------------
// WPN warps per node (each warp owns a 128-float slice for D>=128).
// 4-edge unroll, dual accumulator banks for MLP. Optional fused BN+ReLU.
template <int D, bool ADD, bool ACT>
__global__ void agg_kernel(const float* __restrict__ X, float* __restrict__ Out,
                           const int* __restrict__ rowptr, const int* __restrict__ csr,
                           const float* __restrict__ invdeg, int n_nodes,
                           const float* __restrict__ sc, const float* __restrict__ sh) {
    constexpr int WPN = (D > 128) ? (D / 128) : 1;    // warps per node
    constexpr int PL  = D / (32 * WPN);               // floats per lane (4 or 2)
    int gwarp = (blockIdx.x * blockDim.x + threadIdx.x) >> 5;
    int node = gwarp / WPN;
    int sub  = gwarp - node * WPN;
    if (node >= n_nodes) return;
    int lane = threadIdx.x & 31;
    int doff = sub * 32 * PL + lane * PL;             // element offset in row

    float acc0[PL], acc1[PL];
    float lsc[PL], lsh[PL];
#pragma unroll
    for (int i = 0; i < PL; i++) {
        acc0[i] = 0.0f; acc1[i] = 0.0f;
        if constexpr (ACT) {
            lsc[i] = __ldg(sc + doff + i);
            lsh[i] = __ldg(sh + doff + i);
        }
    }

    int beg = rowptr[node];
    int end = rowptr[node + 1];
    int e = beg;

    if constexpr (PL == 4) {
        for (; e + 3 < end; e += 4) {
            int s0 = __ldg(csr + e);
            int s1 = __ldg(csr + e + 1);
            int s2 = __ldg(csr + e + 2);
            int s3 = __ldg(csr + e + 3);
            float4 v0 = __ldg(reinterpret_cast<const float4*>(X + (size_t)s0 * D + doff));
            float4 v1 = __ldg(reinterpret_cast<const float4*>(X + (size_t)s1 * D + doff));
            float4 v2 = __ldg(reinterpret_cast<const float4*>(X + (size_t)s2 * D + doff));
            float4 v3 = __ldg(reinterpret_cast<const float4*>(X + (size_t)s3 * D + doff));
            if constexpr (ACT) {
                v0.x = fmaxf(v0.x * lsc[0] + lsh[0], 0.f);
                v0.y = fmaxf(v0.y * lsc[1] + lsh[1], 0.f);
                v0.z = fmaxf(v0.z * lsc[2] + lsh[2], 0.f);
                v0.w = fmaxf(v0.w * lsc[3] + lsh[3], 0.f);
                v1.x = fmaxf(v1.x * lsc[0] + lsh[0], 0.f);
                v1.y = fmaxf(v1.y * lsc[1] + lsh[1], 0.f);
                v1.z = fmaxf(v1.z * lsc[2] + lsh[2], 0.f);
                v1.w = fmaxf(v1.w * lsc[3] + lsh[3], 0.f);
                v2.x = fmaxf(v2.x * lsc[0] + lsh[0], 0.f);
                v2.y = fmaxf(v2.y * lsc[1] + lsh[1], 0.f);
                v2.z = fmaxf(v2.z * lsc[2] + lsh[2], 0.f);
                v2.w = fmaxf(v2.w * lsc[3] + lsh[3], 0.f);
                v3.x = fmaxf(v3.x * lsc[0] + lsh[0], 0.f);
                v3.y = fmaxf(v3.y * lsc[1] + lsh[1], 0.f);
                v3.z = fmaxf(v3.z * lsc[2] + lsh[2], 0.f);
                v3.w = fmaxf(v3.w * lsc[3] + lsh[3], 0.f);
            }
            acc0[0] += v0.x + v2.x;  acc1[0] += v1.x + v3.x;
            acc0[1] += v0.y + v2.y;  acc1[1] += v1.y + v3.y;
            acc0[2] += v0.z + v2.z;  acc1[2] += v1.z + v3.z;
            acc0[3] += v0.w + v2.w;  acc1[3] += v1.w + v3.w;
        }
        for (; e < end; e++) {
            int s0 = __ldg(csr + e);
            float4 v0 = __ldg(reinterpret_cast<const float4*>(X + (size_t)s0 * D + doff));
            if constexpr (ACT) {
                v0.x = fmaxf(v0.x * lsc[0] + lsh[0], 0.f);
                v0.y = fmaxf(v0.y * lsc[1] + lsh[1], 0.f);
                v0.z = fmaxf(v0.z * lsc[2] + lsh[2], 0.f);
                v0.w = fmaxf(v0.w * lsc[3] + lsh[3], 0.f);
            }
            acc0[0] += v0.x; acc0[1] += v0.y; acc0[2] += v0.z; acc0[3] += v0.w;
        }
    } else {
        // PL == 2 (D == 64)
        for (; e + 3 < end; e += 4) {
            int s0 = __ldg(csr + e);
            int s1 = __ldg(csr + e + 1);
            int s2 = __ldg(csr + e + 2);
            int s3 = __ldg(csr + e + 3);
            float2 v0 = __ldg(reinterpret_cast<const float2*>(X + (size_t)s0 * D + doff));
            float2 v1 = __ldg(reinterpret_cast<const float2*>(X + (size_t)s1 * D + doff));
            float2 v2 = __ldg(reinterpret_cast<const float2*>(X + (size_t)s2 * D + doff));
            float2 v3 = __ldg(reinterpret_cast<const float2*>(X + (size_t)s3 * D + doff));
            acc0[0] += v0.x + v2.x;  acc1[0] += v1.x + v3.x;
            acc0[1] += v0.y + v2.y;  acc1[1] += v1.y + v3.y;
        }
        for (; e < end; e++) {
            int s0 = __ldg(csr + e);
            float2 v0 = __ldg(reinterpret_cast<const float2*>(X + (size_t)s0 * D + doff));
            acc0[0] += v0.x; acc0[1] += v0.y;
        }
    }

    float w = __ldg(invdeg + node);
    float* o = Out + (size_t)node * D + doff;
#pragma unroll
    for (int i = 0; i < PL; i++) {
        float a = (acc0[i] + acc1[i]) * w;
        if constexpr (ADD) o[i] += a;
        else               o[i]  = a;
    }
}

// ------------------------------ TF32 GEMM -----------------------------------
__device__ __forceinline__ unsigned f2tf32(float f) {
    unsigned u;
    asm("cvt.rna.tf32.f32 %0, %1;" : "=r"(u) : "f"(f));
    return u;
}

__device__ __forceinline__ void mma_tf32(float c[4], const unsigned a[4], const unsigned b[2]) {
    asm volatile(
        "mma.sync.aligned.m16n8k8.row.col.f32.tf32.tf32.f32 "
        "{%0,%1,%2,%3}, {%4,%5,%6,%7}, {%8,%9}, {%0,%1,%2,%3};"
        : "+f"(c[0]), "+f"(c[1]), "+f"(c[2]), "+f"(c[3])
        : "r"(a[0]), "r"(a[1]), "r"(a[2]), "r"(a[3]), "r"(b[0]), "r"(b[1]));
}

// C = act0(A0)@B0 (+ act1(A1)@B1) (+ bias). Dynamic smem, double buffered.
template <int BM, int BN, int WM, int WN>
__global__ void gemm_tf32(const float* __restrict__ A0, const float* __restrict__ B0g,
                          const float* __restrict__ sc0, const float* __restrict__ sh0,
                          const float* __restrict__ A1, const float* __restrict__ B1g,
                          const float* __restrict__ sc1, const float* __restrict__ sh1,
                          float* __restrict__ C, int M, int N, int K,
                          const float* __restrict__ bias) {
    constexpr int BK = 32, THREADS = 256;
    constexpr int WCOLS = BN / WN;
    constexpr int MT = WM / 16, NT = WN / 8;
    constexpr int ACH = (BM * BK) / (4 * THREADS);
    constexpr int BCH = (BK * BN) / (4 * THREADS);
    constexpr int BROWCH = BN / 4;
    constexpr int ASTRIDE = BM + 1;
    constexpr int BSTRIDE = BN + 4;
    static_assert((BM / WM) * (BN / WN) == 8, "8 warps");

    extern __shared__ unsigned smem_u[];
    unsigned* Asm = smem_u;
    unsigned* Bsm = smem_u + 2 * BK * ASTRIDE;
#define AS(b, k, m) Asm[((b) * BK + (k)) * ASTRIDE + (m)]
#define BS(b, k, n) Bsm[((b) * BK + (k)) * BSTRIDE + (n)]

    int tid = threadIdx.x, lane = tid & 31, warp = tid >> 5;
    int wrow = warp / WCOLS, wcol = warp % WCOLS;
    int block_m = blockIdx.y * BM, block_n = blockIdx.x * BN;
    int g = lane >> 2, q = lane & 3;

    float acc[MT][NT][4];
#pragma unroll
    for (int mt = 0; mt < MT; mt++)
#pragma unroll
        for (int nt = 0; nt < NT; nt++)
#pragma unroll
            for (int r = 0; r < 4; r++) acc[mt][nt][r] = 0.0f;

    const int kiters = K / BK;
    const int npass = A1 ? 2 : 1;
    const int total = npass * kiters;

    float4 ra[ACH], rb[BCH];

    auto load_stage = [&](int it) {
        int pass = it / kiters;
        int k0 = (it - pass * kiters) * BK;
        const float* Ap = pass ? A1 : A0;
        const float* Bp = pass ? B1g : B0g;
#pragma unroll
        for (int i = 0; i < ACH; i++) {
            int chunk = tid + i * THREADS;
            int r = chunk >> 3;
            int c4 = (chunk & 7) << 2;
            int gr = block_m + r;
            float4 v = make_float4(0.f, 0.f, 0.f, 0.f);
            if (gr < M)
                v = *reinterpret_cast<const float4*>(Ap + (size_t)gr * K + k0 + c4);
            ra[i] = v;
        }
#pragma unroll
        for (int i = 0; i < BCH; i++) {
            int chunk = tid + i * THREADS;
            int r = chunk / BROWCH;
            int c4 = (chunk % BROWCH) * 4;
            rb[i] = *reinterpret_cast<const float4*>(Bp + (size_t)(k0 + r) * N + block_n + c4);
        }
    };

    auto store_stage = [&](int it, int buf) {
        int pass = it / kiters;
        int k0 = (it - pass * kiters) * BK;
        const float* sc = pass ? sc1 : sc0;
        const float* sh = pass ? sh1 : sh0;
#pragma unroll
        for (int i = 0; i < ACH; i++) {
            int chunk = tid + i * THREADS;
            int r = chunk >> 3;
            int c4 = (chunk & 7) << 2;
            float4 v = ra[i];
            if (sc) {
                float4 s = *reinterpret_cast<const float4*>(sc + k0 + c4);
                float4 t = *reinterpret_cast<const float4*>(sh + k0 + c4);
                v.x = fmaxf(v.x * s.x + t.x, 0.f);
                v.y = fmaxf(v.y * s.y + t.y, 0.f);
                v.z = fmaxf(v.z * s.z + t.z, 0.f);
                v.w = fmaxf(v.w * s.w + t.w, 0.f);
            }
            AS(buf, c4 + 0, r) = f2tf32(v.x);
            AS(buf, c4 + 1, r) = f2tf32(v.y);
            AS(buf, c4 + 2, r) = f2tf32(v.z);
            AS(buf, c4 + 3, r) = f2tf32(v.w);
        }
#pragma unroll
        for (int i = 0; i < BCH; i++) {
            int chunk = tid + i * THREADS;
            int r = chunk / BROWCH;
            int c4 = (chunk % BROWCH) * 4;
            uint4 u;
            u.x = f2tf32(rb[i].x); u.y = f2tf32(rb[i].y);
            u.z = f2tf32(rb[i].z); u.w = f2tf32(rb[i].w);
            *reinterpret_cast<uint4*>(&BS(buf, r, c4)) = u;
        }
    };

    load_stage(0);
    int buf = 0;
    for (int it = 0; it < total; ++it) {
        store_stage(it, buf);
        __syncthreads();
        if (it + 1 < total) load_stage(it + 1);

#pragma unroll
        for (int s = 0; s < BK / 8; ++s) {
            int kq = s * 8 + q;
            unsigned af[MT][4], bf[NT][2];
#pragma unroll
            for (int mt = 0; mt < MT; ++mt) {
                int m = wrow * WM + mt * 16 + g;
                af[mt][0] = AS(buf, kq, m);
                af[mt][1] = AS(buf, kq, m + 8);
                af[mt][2] = AS(buf, kq + 4, m);
                af[mt][3] = AS(buf, kq + 4, m + 8);
            }
#pragma unroll
            for (int nt = 0; nt < NT; ++nt) {
                int nn = wcol * WN + nt * 8 + g;
                bf[nt][0] = BS(buf, kq, nn);
                bf[nt][1] = BS(buf, kq + 4, nn);
            }
#pragma unroll
            for (int mt = 0; mt < MT; ++mt)
#pragma unroll
                for (int nt = 0; nt < NT; ++nt)
                    mma_tf32(acc[mt][nt], af[mt], bf[nt]);
        }
        buf ^= 1;
    }

#pragma unroll
    for (int mt = 0; mt < MT; ++mt) {
        int r0 = block_m + wrow * WM + mt * 16 + g;
        int r1 = r0 + 8;
#pragma unroll
        for (int nt = 0; nt < NT; ++nt) {
            int cn = block_n + wcol * WN + nt * 8 + q * 2;
            float b0 = 0.f, b1 = 0.f;
            if (bias) { b0 = __ldg(bias + cn); b1 = __ldg(bias + cn + 1); }
            if (r0 < M) {
                float2 t0 = make_float2(acc[mt][nt][0] + b0, acc[mt][nt][1] + b1);
                *reinterpret_cast<float2*>(C + (size_t)r0 * N + cn) = t0;
            }
            if (r1 < M) {
                float2 t1 = make_float2(acc[mt][nt][2] + b0, acc[mt][nt][3] + b1);
                *reinterpret_cast<float2*>(C + (size_t)r1 * N + cn) = t1;
            }
        }
    }
#undef AS
#undef BS
}

// ------------------------------- BatchNorm ----------------------------------
__global__ void colstats_partial(const float* __restrict__ H, int M,
                                 float* __restrict__ ps, float* __restrict__ pq) {
    int c = threadIdx.x;
    float s = 0.f, q = 0.f;
    for (int r = blockIdx.x; r < M; r += gridDim.x) {
        float v = H[(size_t)r * HIDDIM + c];
        s += v;
        q += v * v;
    }
    ps[blockIdx.x * HIDDIM + c] = s;
    pq[blockIdx.x * HIDDIM + c] = q;
}

__global__ void colstats_final(const float* __restrict__ ps, const float* __restrict__ pq,
                               int nb, float inv_m,
                               const float* __restrict__ g, const float* __restrict__ be,
                               float* __restrict__ scale, float* __restrict__ shift) {
    int c = threadIdx.x;
    float s = 0.f, q = 0.f;
    for (int b = 0; b < nb; b++) {
        s += ps[b * HIDDIM + c];
        q += pq[b * HIDDIM + c];
    }
    float mu  = s * inv_m;
    float var = q * inv_m - mu * mu;
    float rs  = rsqrtf(var + 1e-5f);
    float sc  = g[c] * rs;
    scale[c] = sc;
    shift[c] = be[c] - mu * sc;
}

// --------------------------------- launch -----------------------------------
extern "C" void kernel_launch(void* const* d_in, const int* in_sizes, int n_in,
                              void* d_out, int out_size) {
    const float* x   = (const float*)d_in[0];
    const int*   ei  = (const int*)d_in[1];
    const float* Wl0 = (const float*)d_in[2];
    const float* bl0 = (const float*)d_in[3];
    const float* Wr0 = (const float*)d_in[4];
    const float* Wl1 = (const float*)d_in[5];
    const float* bl1 = (const float*)d_in[6];
    const float* Wr1 = (const float*)d_in[7];
    const float* Wl2 = (const float*)d_in[8];
    const float* bl2 = (const float*)d_in[9];
    const float* Wr2 = (const float*)d_in[10];
    const float* g0  = (const float*)d_in[11];
    const float* be0 = (const float*)d_in[12];
    const float* g1  = (const float*)d_in[13];
    const float* be1 = (const float*)d_in[14];
    float* out = (float*)d_out;

    const int N  = NNODES;
    const int NE = NEDGES;

    float *agg, *h1, *h2, *y, *invdeg, *ps, *pq, *scale, *shift;
    int *cnt, *rowptr, *fill, *csr;
    cudaGetSymbolAddress((void**)&agg,    g_agg);
    cudaGetSymbolAddress((void**)&h1,     g_h1);
    cudaGetSymbolAddress((void**)&h2,     g_h2);
    cudaGetSymbolAddress((void**)&y,      g_y);
    cudaGetSymbolAddress((void**)&invdeg, g_invdeg);
    cudaGetSymbolAddress((void**)&cnt,    g_cnt);
    cudaGetSymbolAddress((void**)&rowptr, g_rowptr);
    cudaGetSymbolAddress((void**)&fill,   g_fill);
    cudaGetSymbolAddress((void**)&csr,    g_csr);
    cudaGetSymbolAddress((void**)&ps,     g_ps);
    cudaGetSymbolAddress((void**)&pq,     g_pq);
    cudaGetSymbolAddress((void**)&scale,  g_scale);
    cudaGetSymbolAddress((void**)&shift,  g_shift);

    const int SMEM_BIG   = (2 * 32 * (128 + 1) + 2 * 32 * (128 + 4)) * 4;  // 66816 B
    const int SMEM_SMALL = (2 * 32 * (128 + 1) + 2 * 32 * (64 + 4))  * 4;  // 50432 B
    static int smem_set = 0;
    if (!smem_set) {
        cudaFuncSetAttribute(gemm_tf32<128, 128, 64, 32>,
                             cudaFuncAttributeMaxDynamicSharedMemorySize, SMEM_BIG);
        cudaFuncSetAttribute(gemm_tf32<128, 64, 32, 32>,
                             cudaFuncAttributeMaxDynamicSharedMemorySize, SMEM_SMALL);
        smem_set = 1;
    }

    // ---- CSR build ----
    zero_int_kernel<<<(N + 255) / 256, 256>>>(cnt, N);
    hist_kernel<<<(NE + 255) / 256, 256>>>(ei, NE, cnt);
    scan_prep_kernel<<<1, 1024>>>(cnt, rowptr, fill, invdeg, N);
    scatter_kernel<<<(NE + 255) / 256, 256>>>(ei, NE, fill, csr);

    const int AGG_BLOCKS_1W = (N + 7) / 8;          // 1 warp/node (D=64/128)
    const int AGG_BLOCKS_2W = (2 * N + 7) / 8;      // 2 warps/node (D=256)

    // ---- Layer 0: h1 = mean_agg(x) @ Wl0 + x @ Wr0 + bl0  (raw, pre-BN) ----
    agg_kernel<INDIM, false, false><<<AGG_BLOCKS_1W, 256>>>(x, agg, rowptr, csr, invdeg, N, nullptr, nullptr);
    {
        dim3 grid(HIDDIM / 128, (N + 127) / 128);
        gemm_tf32<128, 128, 64, 32><<<grid, 256, SMEM_BIG>>>(agg, Wl0, nullptr, nullptr,
                                                             x,   Wr0, nullptr, nullptr,
                                                             h1, N, HIDDIM, INDIM, bl0);
    }
    colstats_partial<<<NB_STATS, HIDDIM>>>(h1, N, ps, pq);
    colstats_final<<<1, HIDDIM>>>(ps, pq, NB_STATS, 1.0f / (float)N, g0, be0, scale, shift);

    // ---- Layer 1: h2 = mean_agg(act0(h1)) @ Wl1 + act0(h1) @ Wr1 + bl1 ----
    agg_kernel<HIDDIM, false, true><<<AGG_BLOCKS_2W, 256>>>(h1, agg, rowptr, csr, invdeg, N, scale, shift);
    {
        dim3 grid(HIDDIM / 128, (N + 127) / 128);
        gemm_tf32<128, 128, 64, 32><<<grid, 256, SMEM_BIG>>>(agg, Wl1, nullptr, nullptr,
                                                             h1,  Wr1, scale, shift,
                                                             h2, N, HIDDIM, HIDDIM, bl1);
    }
    colstats_partial<<<NB_STATS, HIDDIM>>>(h2, N, ps, pq);
    colstats_final<<<1, HIDDIM>>>(ps, pq, NB_STATS, 1.0f / (float)N, g1, be1, scale, shift);

    // ---- Layer 2: out = mean_agg(act1(h2) @ Wl2) + act1(h2) @ Wr2 + bl2 ----
    {
        dim3 grid(OUTDIM / 64, (N + 127) / 128);
        gemm_tf32<128, 64, 32, 32><<<grid, 256, SMEM_SMALL>>>(h2, Wl2, scale, shift,
                                                              nullptr, nullptr, nullptr, nullptr,
                                                              y, N, OUTDIM, HIDDIM, nullptr);
        gemm_tf32<128, 64, 32, 32><<<grid, 256, SMEM_SMALL>>>(h2, Wr2, scale, shift,
                                                              nullptr, nullptr, nullptr, nullptr,
                                                              out, N, OUTDIM, HIDDIM, bl2);
    }
    agg_kernel<OUTDIM, true, false><<<AGG_BLOCKS_1W, 256>>>(y, out, rowptr, csr, invdeg, N, nullptr, nullptr);
}

// round 7
// speedup vs baseline: 1.5300x; 1.0206x over previous
#include <cuda_runtime.h>
#include <cuda_bf16.h>
#include <cstdint>

// ---------------------------------------------------------------------------
// GraphSAGE (3x SAGEConv + BN/ReLU) on B200 / sm_100a.
//   - CSR built once per launch; reused by all layers.
//   - Layer-1 aggregation gathers a bf16 copy of act0(h1) (positive post-ReLU
//     values -> safe ~2e-4 added error), halving the dominant gather traffic.
//   - Layer-0 / layer-2 aggregations stay fp32 (zero-mean inputs: bf16 unsafe).
//   - GEMM: TF32 mma.sync m16n8k8, dual-A fusion, double-buffered dynamic smem.
//   - Layer 2 trick: mean_agg(act(h2)) @ Wl2 == mean_agg(act(h2) @ Wl2).
// ---------------------------------------------------------------------------

#define NNODES 50000
#define NEDGES 1600000
#define INDIM  128
#define HIDDIM 256
#define OUTDIM 64
#define NB_STATS 512

// ------------------------- scratch (device globals) ------------------------
__device__ float g_agg[(size_t)NNODES * HIDDIM];
__device__ float g_h1 [(size_t)NNODES * HIDDIM];
__device__ float g_h2 [(size_t)NNODES * HIDDIM];
__device__ float g_y  [(size_t)NNODES * OUTDIM];
__device__ __align__(16) __nv_bfloat16 g_h1b[(size_t)NNODES * HIDDIM];  // bf16 act0(h1)
__device__ float g_invdeg[NNODES];
__device__ int   g_cnt[NNODES];
__device__ int   g_rowptr[NNODES + 1];
__device__ int   g_fill[NNODES];
__device__ int   g_csr[NEDGES];
__device__ float g_ps[NB_STATS * HIDDIM];
__device__ float g_pq[NB_STATS * HIDDIM];
__device__ __align__(16) float g_scale[HIDDIM];
__device__ __align__(16) float g_shift[HIDDIM];

// ------------------------------- CSR build ---------------------------------
__global__ void zero_int_kernel(int* p, int n) {
    int i = blockIdx.x * blockDim.x + threadIdx.x;
    if (i < n) p[i] = 0;
}

__global__ void hist_kernel(const int* __restrict__ ei, int ne, int* __restrict__ cnt) {
    int e = blockIdx.x * blockDim.x + threadIdx.x;
    if (e < ne) {
        int d = ei[ne + e];
        if ((unsigned)d < (unsigned)NNODES)
            atomicAdd(&cnt[d], 1);
    }
}

__global__ void scan_prep_kernel(const int* __restrict__ cnt, int* __restrict__ rowptr,
                                 int* __restrict__ fill, float* __restrict__ invdeg, int n) {
    __shared__ int wsum[32];
    __shared__ int carry_s;
    int tid = threadIdx.x, lane = tid & 31, wid = tid >> 5;
    if (tid == 0) { carry_s = 0; rowptr[0] = 0; }
    __syncthreads();
    for (int base = 0; base < n; base += 1024) {
        int i = base + tid;
        int v = (i < n) ? cnt[i] : 0;
        int s = v;
#pragma unroll
        for (int off = 1; off < 32; off <<= 1) {
            int t = __shfl_up_sync(0xffffffffu, s, off);
            if (lane >= off) s += t;
        }
        if (lane == 31) wsum[wid] = s;
        __syncthreads();
        if (wid == 0) {
            int w = wsum[lane];
#pragma unroll
            for (int off = 1; off < 32; off <<= 1) {
                int t = __shfl_up_sync(0xffffffffu, w, off);
                if (lane >= off) w += t;
            }
            wsum[lane] = w;
        }
        __syncthreads();
        int incl = s + (wid ? wsum[wid - 1] : 0) + carry_s;
        if (i < n) {
            rowptr[i + 1] = incl;
            fill[i] = incl - v;
            invdeg[i] = 1.0f / (float)(v > 0 ? v : 1);
        }
        __syncthreads();
        if (tid == 1023) carry_s = incl;
        __syncthreads();
    }
}

__global__ void scatter_kernel(const int* __restrict__ ei, int ne,
                               int* __restrict__ fill, int* __restrict__ csr) {
    int e = blockIdx.x * blockDim.x + threadIdx.x;
    if (e < ne) {
        int s = ei[e];
        int d = ei[ne + e];
        if ((unsigned)d < (unsigned)NNODES && (unsigned)s < (unsigned)NNODES) {
            int pos = atomicAdd(&fill[d], 1);
            if ((unsigned)pos < (unsigned)NEDGES)
                csr[pos] = s;
        }
    }
}

// ------------------------- act -> bf16 conversion ---------------------------
// h1b[i] = bf16( max(h1[i]*scale[col] + shift[col], 0) )
__global__ void act_bf16_kernel(const float4* __restrict__ H, __nv_bfloat162* __restrict__ O2,
                                int n4, const float* __restrict__ sc, const float* __restrict__ sh) {
    int i = blockIdx.x * blockDim.x + threadIdx.x;
    if (i >= n4) return;
    int c = (i * 4) & (HIDDIM - 1);
    float4 v = H[i];
    v.x = fmaxf(v.x * __ldg(sc + c + 0) + __ldg(sh + c + 0), 0.f);
    v.y = fmaxf(v.y * __ldg(sc + c + 1) + __ldg(sh + c + 1), 0.f);
    v.z = fmaxf(v.z * __ldg(sc + c + 2) + __ldg(sh + c + 2), 0.f);
    v.w = fmaxf(v.w * __ldg(sc + c + 3) + __ldg(sh + c + 3), 0.f);
    O2[i * 2 + 0] = __floats2bfloat162_rn(v.x, v.y);
    O2[i * 2 + 1] = __floats2bfloat162_rn(v.z, v.w);
}

// ------------------------- bf16 aggregation (D=256) -------------------------
// One warp per node; lane owns 8 contiguous bf16 (16B). 4-edge unroll, fp32 acc.
__global__ void agg256_bf16_kernel(const __nv_bfloat16* __restrict__ Xb, float* __restrict__ Out,
                                   const int* __restrict__ rowptr, const int* __restrict__ csr,
                                   const float* __restrict__ invdeg, int n_nodes) {
    int node = (blockIdx.x * blockDim.x + threadIdx.x) >> 5;
    if (node >= n_nodes) return;
    int lane = threadIdx.x & 31;
    int doff = lane * 8;

    float acc0[8], acc1[8];
#pragma unroll
    for (int i = 0; i < 8; i++) { acc0[i] = 0.f; acc1[i] = 0.f; }

    int beg = rowptr[node];
    int end = rowptr[node + 1];
    int e = beg;

    auto accum = [&](uint4 u, float* acc) {
        __nv_bfloat162 b0 = *reinterpret_cast<__nv_bfloat162*>(&u.x);
        __nv_bfloat162 b1 = *reinterpret_cast<__nv_bfloat162*>(&u.y);
        __nv_bfloat162 b2 = *reinterpret_cast<__nv_bfloat162*>(&u.z);
        __nv_bfloat162 b3 = *reinterpret_cast<__nv_bfloat162*>(&u.w);
        float2 f0 = __bfloat1622float2(b0);
        float2 f1 = __bfloat1622float2(b1);
        float2 f2 = __bfloat1622float2(b2);
        float2 f3 = __bfloat1622float2(b3);
        acc[0] += f0.x; acc[1] += f0.y;
        acc[2] += f1.x; acc[3] += f1.y;
        acc[4] += f2.x; acc[5] += f2.y;
        acc[6] += f3.x; acc[7] += f3.y;
    };

    for (; e + 3 < end; e += 4) {
        int s0 = __ldg(csr + e);
        int s1 = __ldg(csr + e + 1);
        int s2 = __ldg(csr + e + 2);
        int s3 = __ldg(csr + e + 3);
        uint4 u0 = __ldg(reinterpret_cast<const uint4*>(Xb + (size_t)s0 * HIDDIM + doff));
        uint4 u1 = __ldg(reinterpret_cast<const uint4*>(Xb + (size_t)s1 * HIDDIM + doff));
        uint4 u2 = __ldg(reinterpret_cast<const uint4*>(Xb + (size_t)s2 * HIDDIM + doff));
        uint4 u3 = __ldg(reinterpret_cast<const uint4*>(Xb + (size_t)s3 * HIDDIM + doff));
        accum(u0, acc0); accum(u1, acc1); accum(u2, acc0); accum(u3, acc1);
    }
    for (; e < end; e++) {
        int s0 = __ldg(csr + e);
        uint4 u0 = __ldg(reinterpret_cast<const uint4*>(Xb + (size_t)s0 * HIDDIM + doff));
        accum(u0, acc0);
    }

    float w = __ldg(invdeg + node);
    float* o = Out + (size_t)node * HIDDIM + doff;
    float4 o0 = make_float4((acc0[0] + acc1[0]) * w, (acc0[1] + acc1[1]) * w,
                            (acc0[2] + acc1[2]) * w, (acc0[3] + acc1[3]) * w);
    float4 o1 = make_float4((acc0[4] + acc1[4]) * w, (acc0[5] + acc1[5]) * w,
                            (acc0[6] + acc1[6]) * w, (acc0[7] + acc1[7]) * w);
    *reinterpret_cast<float4*>(o)     = o0;
    *reinterpret_cast<float4*>(o + 4) = o1;
}

// ------------------------ fp32 aggregation (D=64/128) -----------------------
template <int D, bool ADD>
__global__ void agg_kernel(const float* __restrict__ X, float* __restrict__ Out,
                           const int* __restrict__ rowptr, const int* __restrict__ csr,
                           const float* __restrict__ invdeg, int n_nodes) {
    constexpr int PL = D / 32;
    int node = (blockIdx.x * blockDim.x + threadIdx.x) >> 5;
    if (node >= n_nodes) return;
    int lane = threadIdx.x & 31;
    int doff = lane * PL;

    float acc0[PL], acc1[PL];
#pragma unroll
    for (int i = 0; i < PL; i++) { acc0[i] = 0.f; acc1[i] = 0.f; }

    int beg = rowptr[node];
    int end = rowptr[node + 1];
    int e = beg;

    if constexpr (PL == 4) {
        for (; e + 3 < end; e += 4) {
            int s0 = __ldg(csr + e);
            int s1 = __ldg(csr + e + 1);
            int s2 = __ldg(csr + e + 2);
            int s3 = __ldg(csr + e + 3);
            float4 v0 = __ldg(reinterpret_cast<const float4*>(X + (size_t)s0 * D + doff));
            float4 v1 = __ldg(reinterpret_cast<const float4*>(X + (size_t)s1 * D + doff));
            float4 v2 = __ldg(reinterpret_cast<const float4*>(X + (size_t)s2 * D + doff));
            float4 v3 = __ldg(reinterpret_cast<const float4*>(X + (size_t)s3 * D + doff));
            acc0[0] += v0.x + v2.x;  acc1[0] += v1.x + v3.x;
            acc0[1] += v0.y + v2.y;  acc1[1] += v1.y + v3.y;
            acc0[2] += v0.z + v2.z;  acc1[2] += v1.z + v3.z;
            acc0[3] += v0.w + v2.w;  acc1[3] += v1.w + v3.w;
        }
        for (; e < end; e++) {
            int s0 = __ldg(csr + e);
            float4 v0 = __ldg(reinterpret_cast<const float4*>(X + (size_t)s0 * D + doff));
            acc0[0] += v0.x; acc0[1] += v0.y; acc0[2] += v0.z; acc0[3] += v0.w;
        }
    } else {
        for (; e + 3 < end; e += 4) {
            int s0 = __ldg(csr + e);
            int s1 = __ldg(csr + e + 1);
            int s2 = __ldg(csr + e + 2);
            int s3 = __ldg(csr + e + 3);
            float2 v0 = __ldg(reinterpret_cast<const float2*>(X + (size_t)s0 * D + doff));
            float2 v1 = __ldg(reinterpret_cast<const float2*>(X + (size_t)s1 * D + doff));
            float2 v2 = __ldg(reinterpret_cast<const float2*>(X + (size_t)s2 * D + doff));
            float2 v3 = __ldg(reinterpret_cast<const float2*>(X + (size_t)s3 * D + doff));
            acc0[0] += v0.x + v2.x;  acc1[0] += v1.x + v3.x;
            acc0[1] += v0.y + v2.y;  acc1[1] += v1.y + v3.y;
        }
        for (; e < end; e++) {
            int s0 = __ldg(csr + e);
            float2 v0 = __ldg(reinterpret_cast<const float2*>(X + (size_t)s0 * D + doff));
            acc0[0] += v0.x; acc0[1] += v0.y;
        }
    }

    float w = __ldg(invdeg + node);
    float* o = Out + (size_t)node * D + doff;
#pragma unroll
    for (int i = 0; i < PL; i++) {
        float a = (acc0[i] + acc1[i]) * w;
        if constexpr (ADD) o[i] += a;
        else               o[i]  = a;
    }
}

// ------------------------------ TF32 GEMM -----------------------------------
__device__ __forceinline__ unsigned f2tf32(float f) {
    unsigned u;
    asm("cvt.rna.tf32.f32 %0, %1;" : "=r"(u) : "f"(f));
    return u;
}

__device__ __forceinline__ void mma_tf32(float c[4], const unsigned a[4], const unsigned b[2]) {
    asm volatile(
        "mma.sync.aligned.m16n8k8.row.col.f32.tf32.tf32.f32 "
        "{%0,%1,%2,%3}, {%4,%5,%6,%7}, {%8,%9}, {%0,%1,%2,%3};"
        : "+f"(c[0]), "+f"(c[1]), "+f"(c[2]), "+f"(c[3])
        : "r"(a[0]), "r"(a[1]), "r"(a[2]), "r"(a[3]), "r"(b[0]), "r"(b[1]));
}

template <int BM, int BN, int WM, int WN>
__global__ void gemm_tf32(const float* __restrict__ A0, const float* __restrict__ B0g,
                          const float* __restrict__ sc0, const float* __restrict__ sh0,
                          const float* __restrict__ A1, const float* __restrict__ B1g,
                          const float* __restrict__ sc1, const float* __restrict__ sh1,
                          float* __restrict__ C, int M, int N, int K,
                          const float* __restrict__ bias) {
    constexpr int BK = 32, THREADS = 256;
    constexpr int WCOLS = BN / WN;
    constexpr int MT = WM / 16, NT = WN / 8;
    constexpr int ACH = (BM * BK) / (4 * THREADS);
    constexpr int BCH = (BK * BN) / (4 * THREADS);
    constexpr int BROWCH = BN / 4;
    constexpr int ASTRIDE = BM + 1;
    constexpr int BSTRIDE = BN + 4;
    static_assert((BM / WM) * (BN / WN) == 8, "8 warps");

    extern __shared__ unsigned smem_u[];
    unsigned* Asm = smem_u;
    unsigned* Bsm = smem_u + 2 * BK * ASTRIDE;
#define AS(b, k, m) Asm[((b) * BK + (k)) * ASTRIDE + (m)]
#define BS(b, k, n) Bsm[((b) * BK + (k)) * BSTRIDE + (n)]

    int tid = threadIdx.x, lane = tid & 31, warp = tid >> 5;
    int wrow = warp / WCOLS, wcol = warp % WCOLS;
    int block_m = blockIdx.y * BM, block_n = blockIdx.x * BN;
    int g = lane >> 2, q = lane & 3;

    float acc[MT][NT][4];
#pragma unroll
    for (int mt = 0; mt < MT; mt++)
#pragma unroll
        for (int nt = 0; nt < NT; nt++)
#pragma unroll
            for (int r = 0; r < 4; r++) acc[mt][nt][r] = 0.0f;

    const int kiters = K / BK;
    const int npass = A1 ? 2 : 1;
    const int total = npass * kiters;

    float4 ra[ACH], rb[BCH];

    auto load_stage = [&](int it) {
        int pass = it / kiters;
        int k0 = (it - pass * kiters) * BK;
        const float* Ap = pass ? A1 : A0;
        const float* Bp = pass ? B1g : B0g;
#pragma unroll
        for (int i = 0; i < ACH; i++) {
            int chunk = tid + i * THREADS;
            int r = chunk >> 3;
            int c4 = (chunk & 7) << 2;
            int gr = block_m + r;
            float4 v = make_float4(0.f, 0.f, 0.f, 0.f);
            if (gr < M)
                v = *reinterpret_cast<const float4*>(Ap + (size_t)gr * K + k0 + c4);
            ra[i] = v;
        }
#pragma unroll
        for (int i = 0; i < BCH; i++) {
            int chunk = tid + i * THREADS;
            int r = chunk / BROWCH;
            int c4 = (chunk % BROWCH) * 4;
            rb[i] = *reinterpret_cast<const float4*>(Bp + (size_t)(k0 + r) * N + block_n + c4);
        }
    };

    auto store_stage = [&](int it, int buf) {
        int pass = it / kiters;
        int k0 = (it - pass * kiters) * BK;
        const float* sc = pass ? sc1 : sc0;
        const float* sh = pass ? sh1 : sh0;
#pragma unroll
        for (int i = 0; i < ACH; i++) {
            int chunk = tid + i * THREADS;
            int r = chunk >> 3;
            int c4 = (chunk & 7) << 2;
            float4 v = ra[i];
            if (sc) {
                float4 s = *reinterpret_cast<const float4*>(sc + k0 + c4);
                float4 t = *reinterpret_cast<const float4*>(sh + k0 + c4);
                v.x = fmaxf(v.x * s.x + t.x, 0.f);
                v.y = fmaxf(v.y * s.y + t.y, 0.f);
                v.z = fmaxf(v.z * s.z + t.z, 0.f);
                v.w = fmaxf(v.w * s.w + t.w, 0.f);
            }
            AS(buf, c4 + 0, r) = f2tf32(v.x);
            AS(buf, c4 + 1, r) = f2tf32(v.y);
            AS(buf, c4 + 2, r) = f2tf32(v.z);
            AS(buf, c4 + 3, r) = f2tf32(v.w);
        }
#pragma unroll
        for (int i = 0; i < BCH; i++) {
            int chunk = tid + i * THREADS;
            int r = chunk / BROWCH;
            int c4 = (chunk % BROWCH) * 4;
            uint4 u;
            u.x = f2tf32(rb[i].x); u.y = f2tf32(rb[i].y);
            u.z = f2tf32(rb[i].z); u.w = f2tf32(rb[i].w);
            *reinterpret_cast<uint4*>(&BS(buf, r, c4)) = u;
        }
    };

    load_stage(0);
    int buf = 0;
    for (int it = 0; it < total; ++it) {
        store_stage(it, buf);
        __syncthreads();
        if (it + 1 < total) load_stage(it + 1);

#pragma unroll
        for (int s = 0; s < BK / 8; ++s) {
            int kq = s * 8 + q;
            unsigned af[MT][4], bf[NT][2];
#pragma unroll
            for (int mt = 0; mt < MT; ++mt) {
                int m = wrow * WM + mt * 16 + g;
                af[mt][0] = AS(buf, kq, m);
                af[mt][1] = AS(buf, kq, m + 8);
                af[mt][2] = AS(buf, kq + 4, m);
                af[mt][3] = AS(buf, kq + 4, m + 8);
            }
#pragma unroll
            for (int nt = 0; nt < NT; ++nt) {
                int nn = wcol * WN + nt * 8 + g;
                bf[nt][0] = BS(buf, kq, nn);
                bf[nt][1] = BS(buf, kq + 4, nn);
            }
#pragma unroll
            for (int mt = 0; mt < MT; ++mt)
#pragma unroll
                for (int nt = 0; nt < NT; ++nt)
                    mma_tf32(acc[mt][nt], af[mt], bf[nt]);
        }
        buf ^= 1;
    }

#pragma unroll
    for (int mt = 0; mt < MT; ++mt) {
        int r0 = block_m + wrow * WM + mt * 16 + g;
        int r1 = r0 + 8;
#pragma unroll
        for (int nt = 0; nt < NT; ++nt) {
            int cn = block_n + wcol * WN + nt * 8 + q * 2;
            float b0 = 0.f, b1 = 0.f;
            if (bias) { b0 = __ldg(bias + cn); b1 = __ldg(bias + cn + 1); }
            if (r0 < M) {
                float2 t0 = make_float2(acc[mt][nt][0] + b0, acc[mt][nt][1] + b1);
                *reinterpret_cast<float2*>(C + (size_t)r0 * N + cn) = t0;
            }
            if (r1 < M) {
                float2 t1 = make_float2(acc[mt][nt][2] + b0, acc[mt][nt][3] + b1);
                *reinterpret_cast<float2*>(C + (size_t)r1 * N + cn) = t1;
            }
        }
    }
#undef AS
#undef BS
}

// ------------------------------- BatchNorm ----------------------------------
__global__ void colstats_partial(const float* __restrict__ H, int M,
                                 float* __restrict__ ps, float* __restrict__ pq) {
    int c = threadIdx.x;
    float s = 0.f, q = 0.f;
    for (int r = blockIdx.x; r < M; r += gridDim.x) {
        float v = H[(size_t)r * HIDDIM + c];
        s += v;
        q += v * v;
    }
    ps[blockIdx.x * HIDDIM + c] = s;
    pq[blockIdx.x * HIDDIM + c] = q;
}

__global__ void colstats_final(const float* __restrict__ ps, const float* __restrict__ pq,
                               int nb, float inv_m,
                               const float* __restrict__ g, const float* __restrict__ be,
                               float* __restrict__ scale, float* __restrict__ shift) {
    int c = threadIdx.x;
    float s = 0.f, q = 0.f;
    for (int b = 0; b < nb; b++) {
        s += ps[b * HIDDIM + c];
        q += pq[b * HIDDIM + c];
    }
    float mu  = s * inv_m;
    float var = q * inv_m - mu * mu;
    float rs  = rsqrtf(var + 1e-5f);
    float sc  = g[c] * rs;
    scale[c] = sc;
    shift[c] = be[c] - mu * sc;
}

// --------------------------------- launch -----------------------------------
extern "C" void kernel_launch(void* const* d_in, const int* in_sizes, int n_in,
                              void* d_out, int out_size) {
    const float* x   = (const float*)d_in[0];
    const int*   ei  = (const int*)d_in[1];
    const float* Wl0 = (const float*)d_in[2];
    const float* bl0 = (const float*)d_in[3];
    const float* Wr0 = (const float*)d_in[4];
    const float* Wl1 = (const float*)d_in[5];
    const float* bl1 = (const float*)d_in[6];
    const float* Wr1 = (const float*)d_in[7];
    const float* Wl2 = (const float*)d_in[8];
    const float* bl2 = (const float*)d_in[9];
    const float* Wr2 = (const float*)d_in[10];
    const float* g0  = (const float*)d_in[11];
    const float* be0 = (const float*)d_in[12];
    const float* g1  = (const float*)d_in[13];
    const float* be1 = (const float*)d_in[14];
    float* out = (float*)d_out;

    const int N  = NNODES;
    const int NE = NEDGES;

    float *agg, *h1, *h2, *y, *invdeg, *ps, *pq, *scale, *shift;
    __nv_bfloat16* h1b;
    int *cnt, *rowptr, *fill, *csr;
    cudaGetSymbolAddress((void**)&agg,    g_agg);
    cudaGetSymbolAddress((void**)&h1,     g_h1);
    cudaGetSymbolAddress((void**)&h2,     g_h2);
    cudaGetSymbolAddress((void**)&y,      g_y);
    cudaGetSymbolAddress((void**)&h1b,    g_h1b);
    cudaGetSymbolAddress((void**)&invdeg, g_invdeg);
    cudaGetSymbolAddress((void**)&cnt,    g_cnt);
    cudaGetSymbolAddress((void**)&rowptr, g_rowptr);
    cudaGetSymbolAddress((void**)&fill,   g_fill);
    cudaGetSymbolAddress((void**)&csr,    g_csr);
    cudaGetSymbolAddress((void**)&ps,     g_ps);
    cudaGetSymbolAddress((void**)&pq,     g_pq);
    cudaGetSymbolAddress((void**)&scale,  g_scale);
    cudaGetSymbolAddress((void**)&shift,  g_shift);

    const int SMEM_BIG   = (2 * 32 * (128 + 1) + 2 * 32 * (128 + 4)) * 4;  // 66816 B
    const int SMEM_SMALL = (2 * 32 * (128 + 1) + 2 * 32 * (64 + 4))  * 4;  // 50432 B
    static int smem_set = 0;
    if (!smem_set) {
        cudaFuncSetAttribute(gemm_tf32<128, 128, 64, 32>,
                             cudaFuncAttributeMaxDynamicSharedMemorySize, SMEM_BIG);
        cudaFuncSetAttribute(gemm_tf32<128, 64, 32, 32>,
                             cudaFuncAttributeMaxDynamicSharedMemorySize, SMEM_SMALL);
        smem_set = 1;
    }

    // ---- CSR build ----
    zero_int_kernel<<<(N + 255) / 256, 256>>>(cnt, N);
    hist_kernel<<<(NE + 255) / 256, 256>>>(ei, NE, cnt);
    scan_prep_kernel<<<1, 1024>>>(cnt, rowptr, fill, invdeg, N);
    scatter_kernel<<<(NE + 255) / 256, 256>>>(ei, NE, fill, csr);

    const int AGG_BLOCKS = (N + 7) / 8;      // 1 warp/node, 256-thread blocks

    // ---- Layer 0: h1 = mean_agg(x) @ Wl0 + x @ Wr0 + bl0  (raw, pre-BN) ----
    agg_kernel<INDIM, false><<<AGG_BLOCKS, 256>>>(x, agg, rowptr, csr, invdeg, N);
    {
        dim3 grid(HIDDIM / 128, (N + 127) / 128);
        gemm_tf32<128, 128, 64, 32><<<grid, 256, SMEM_BIG>>>(agg, Wl0, nullptr, nullptr,
                                                             x,   Wr0, nullptr, nullptr,
                                                             h1, N, HIDDIM, INDIM, bl0);
    }
    colstats_partial<<<NB_STATS, HIDDIM>>>(h1, N, ps, pq);
    colstats_final<<<1, HIDDIM>>>(ps, pq, NB_STATS, 1.0f / (float)N, g0, be0, scale, shift);

    // ---- Layer 1: h2 = mean_agg(act0(h1)) @ Wl1 + act0(h1) @ Wr1 + bl1 ----
    // act0(h1) materialized once as bf16 (positive values -> safe rounding);
    // aggregation gathers bf16 (half traffic), accumulates fp32.
    act_bf16_kernel<<<(N * HIDDIM / 4 + 255) / 256, 256>>>(
        (const float4*)h1, (__nv_bfloat162*)h1b, N * HIDDIM / 4, scale, shift);
    agg256_bf16_kernel<<<AGG_BLOCKS, 256>>>(h1b, agg, rowptr, csr, invdeg, N);
    {
        dim3 grid(HIDDIM / 128, (N + 127) / 128);
        gemm_tf32<128, 128, 64, 32><<<grid, 256, SMEM_BIG>>>(agg, Wl1, nullptr, nullptr,
                                                             h1,  Wr1, scale, shift,
                                                             h2, N, HIDDIM, HIDDIM, bl1);
    }
    colstats_partial<<<NB_STATS, HIDDIM>>>(h2, N, ps, pq);
    colstats_final<<<1, HIDDIM>>>(ps, pq, NB_STATS, 1.0f / (float)N, g1, be1, scale, shift);

    // ---- Layer 2: out = mean_agg(act1(h2) @ Wl2) + act1(h2) @ Wr2 + bl2 ----
    {
        dim3 grid(OUTDIM / 64, (N + 127) / 128);
        gemm_tf32<128, 64, 32, 32><<<grid, 256, SMEM_SMALL>>>(h2, Wl2, scale, shift,
                                                              nullptr, nullptr, nullptr, nullptr,
                                                              y, N, OUTDIM, HIDDIM, nullptr);
        gemm_tf32<128, 64, 32, 32><<<grid, 256, SMEM_SMALL>>>(h2, Wr2, scale, shift,
                                                              nullptr, nullptr, nullptr, nullptr,
                                                              out, N, OUTDIM, HIDDIM, bl2);
    }
    agg_kernel<OUTDIM, true><<<AGG_BLOCKS, 256>>>(y, out, rowptr, csr, invdeg, N);
}